// round 7
// baseline (speedup 1.0000x reference)
#include <cuda_runtime.h>
#include <math_constants.h>
#include <cstdint>

#define NNODES 100000
#define NEDGES 1600000

// ---------------- scratch (static __device__ — no allocs allowed) ----------------
__device__ float g_m[(size_t)NNODES * 384];       // projected messages [N][3*128]
__device__ float g_feats[(size_t)NNODES * 1536];  // PNA features [N][3*512]
__device__ int   g_rowptr[NNODES + 1];

// ---------------- cp.async helpers ----------------
__device__ __forceinline__ void cpasync16(unsigned int dst, const float* src) {
    asm volatile("cp.async.cg.shared.global [%0], [%1], 16;\n" :: "r"(dst), "l"(src));
}
__device__ __forceinline__ void cp_commit() {
    asm volatile("cp.async.commit_group;\n" ::);
}
__device__ __forceinline__ void cp_wait1() {
    asm volatile("cp.async.wait_group 1;\n" ::);
}

// ---------------- tf32 helpers ----------------
__device__ __forceinline__ unsigned f2tf32(float f) {
    unsigned r;
    asm("cvt.rna.tf32.f32 %0, %1;" : "=r"(r) : "f"(f));
    return r;
}
__device__ __forceinline__ void mma_tf32(float* d, const unsigned* a, const unsigned* b) {
    asm volatile(
        "mma.sync.aligned.m16n8k8.row.col.f32.tf32.tf32.f32 "
        "{%0,%1,%2,%3},{%4,%5,%6,%7},{%8,%9},{%0,%1,%2,%3};\n"
        : "+f"(d[0]), "+f"(d[1]), "+f"(d[2]), "+f"(d[3])
        : "r"(a[0]), "r"(a[1]), "r"(a[2]), "r"(a[3]), "r"(b[0]), "r"(b[1]));
}

// ---------------- row pointers from sorted rows ----------------
__global__ void k_rowptr(const int* __restrict__ rows, int E, int N) {
    int i = blockIdx.x * blockDim.x + threadIdx.x;
    if (i > N) return;
    int lo = 0, hi = E;
    while (lo < hi) {
        int mid = (lo + hi) >> 1;
        if (__ldg(rows + mid) < i) lo = mid + 1; else hi = mid;
    }
    g_rowptr[i] = lo;
}

// ---------------- GEMM inner: 4-k group, vectorized A+B reads (fp32 SIMT) ----------------
#define GEMM_COMPUTE_CHUNK(ASBUF, BSBUF)                                          \
    _Pragma("unroll")                                                             \
    for (int g = 0; g < 4; g++) {                                                 \
        float4 b0[4], b1[4];                                                      \
        _Pragma("unroll")                                                         \
        for (int k = 0; k < 4; k++) {                                             \
            b0[k] = *(const float4*)&(BSBUF)[g * 4 + k][col0];                    \
            b1[k] = *(const float4*)&(BSBUF)[g * 4 + k][col0 + 4];                \
        }                                                                         \
        _Pragma("unroll")                                                         \
        for (int r = 0; r < 8; r++) {                                             \
            float4 a = *(const float4*)&(ASBUF)[row0 + r][g * 4];                 \
            float av[4] = {a.x, a.y, a.z, a.w};                                   \
            _Pragma("unroll")                                                     \
            for (int k = 0; k < 4; k++) {                                         \
                acc[r][0] += av[k] * b0[k].x; acc[r][1] += av[k] * b0[k].y;       \
                acc[r][2] += av[k] * b0[k].z; acc[r][3] += av[k] * b0[k].w;       \
                acc[r][4] += av[k] * b1[k].x; acc[r][5] += av[k] * b1[k].y;       \
                acc[r][6] += av[k] * b1[k].z; acc[r][7] += av[k] * b1[k].w;       \
            }                                                                     \
        }                                                                         \
    }

// ---------------- projection GEMM: m = x @ [W | W2 | W3] (fp32 SIMT) ----------------
__global__ __launch_bounds__(256, 2) void k_proj(const float* __restrict__ x,
                                                 const float* __restrict__ W,
                                                 const float* __restrict__ W2,
                                                 const float* __restrict__ W3, int N) {
    __shared__ float As[2][128][16];
    __shared__ float Bs[2][16][128];
    const int bm = blockIdx.x * 128;
    const int slab = blockIdx.y;  // 0..2
    const float* Wp = (slab == 0) ? W : (slab == 1) ? W2 : W3;
    const int tid = threadIdx.x;
    const int tx = tid & 15, ty = tid >> 4;
    const int row0 = ty * 8, col0 = tx * 8;

    const int ar0  = tid >> 2;
    const int akq  = (tid & 3) << 2;
    const int bkk0 = tid >> 5;
    const int bjq  = (tid & 31) << 2;

    int gr0 = bm + ar0;      if (gr0 >= N) gr0 = N - 1;
    int gr1 = bm + ar0 + 64; if (gr1 >= N) gr1 = N - 1;
    const float* sA0 = x + (size_t)gr0 * 128 + akq;
    const float* sA1 = x + (size_t)gr1 * 128 + akq;
    const float* sB0 = Wp + (size_t)bkk0 * 128 + bjq;
    const float* sB1 = Wp + (size_t)(bkk0 + 8) * 128 + bjq;

    const unsigned int dA0 = (unsigned int)__cvta_generic_to_shared(&As[0][ar0][akq]);
    const unsigned int dA1 = (unsigned int)__cvta_generic_to_shared(&As[0][ar0 + 64][akq]);
    const unsigned int dB0 = (unsigned int)__cvta_generic_to_shared(&Bs[0][bkk0][bjq]);
    const unsigned int dB1 = (unsigned int)__cvta_generic_to_shared(&Bs[0][bkk0 + 8][bjq]);

    const int NK = 8;
#pragma unroll
    for (int p = 0; p < 2; p++) {
        cpasync16(dA0 + p * 8192, sA0 + p * 16);
        cpasync16(dA1 + p * 8192, sA1 + p * 16);
        cpasync16(dB0 + p * 8192, sB0 + (size_t)p * 2048);
        cpasync16(dB1 + p * 8192, sB1 + (size_t)p * 2048);
        cp_commit();
    }

    float acc[8][8] = {};
    for (int i = 0; i < NK; i++) {
        cp_wait1();
        __syncthreads();
        const int buf = i & 1;
        if (buf == 0) { GEMM_COMPUTE_CHUNK(As[0], Bs[0]); }
        else          { GEMM_COMPUTE_CHUNK(As[1], Bs[1]); }
        __syncthreads();
        const int nc = i + 2;
        if (nc < NK) {
            cpasync16(dA0 + buf * 8192, sA0 + nc * 16);
            cpasync16(dA1 + buf * 8192, sA1 + nc * 16);
            cpasync16(dB0 + buf * 8192, sB0 + (size_t)nc * 2048);
            cpasync16(dB1 + buf * 8192, sB1 + (size_t)nc * 2048);
        }
        cp_commit();
    }

    const int colg = slab * 128 + col0;
#pragma unroll
    for (int i = 0; i < 8; i++) {
        int gr = bm + row0 + i;
        if (gr < N) {
            float4 o0 = make_float4(acc[i][0], acc[i][1], acc[i][2], acc[i][3]);
            float4 o1 = make_float4(acc[i][4], acc[i][5], acc[i][6], acc[i][7]);
            *(float4*)&g_m[(size_t)gr * 384 + colg]     = o0;
            *(float4*)&g_m[(size_t)gr * 384 + colg + 4] = o1;
        }
    }
}

// ---------------- aggregation: warp-per-node segment mean/max/min/std ----------------
__device__ __forceinline__ void agg_upd(float4 v, float s, float4& su, float4& sq,
                                        float4& mx, float4& mn) {
    float gx = v.x * s, gy = v.y * s, gz = v.z * s, gw = v.w * s;
    su.x += gx; su.y += gy; su.z += gz; su.w += gw;
    sq.x += gx * gx; sq.y += gy * gy; sq.z += gz * gz; sq.w += gw * gw;
    mx.x = fmaxf(mx.x, gx); mx.y = fmaxf(mx.y, gy); mx.z = fmaxf(mx.z, gz); mx.w = fmaxf(mx.w, gw);
    mn.x = fminf(mn.x, gx); mn.y = fminf(mn.y, gy); mn.z = fminf(mn.z, gz); mn.w = fminf(mn.w, gw);
}

__device__ __forceinline__ void agg_finish(int deg, float inv, float4 su, float4 sq,
                                           float4 mx, float4 mn, float* base) {
    float4 mean, var, sd;
    mean.x = su.x * inv; mean.y = su.y * inv; mean.z = su.z * inv; mean.w = su.w * inv;
    var.x = fmaxf(sq.x * inv - mean.x * mean.x, 0.f);
    var.y = fmaxf(sq.y * inv - mean.y * mean.y, 0.f);
    var.z = fmaxf(sq.z * inv - mean.z * mean.z, 0.f);
    var.w = fmaxf(sq.w * inv - mean.w * mean.w, 0.f);
    sd.x = sqrtf(var.x + 1e-5f); sd.y = sqrtf(var.y + 1e-5f);
    sd.z = sqrtf(var.z + 1e-5f); sd.w = sqrtf(var.w + 1e-5f);
    if (deg == 0) {
        mx = make_float4(0.f, 0.f, 0.f, 0.f);
        mn = make_float4(0.f, 0.f, 0.f, 0.f);
    }
    *(float4*)(base)       = mean;
    *(float4*)(base + 128) = mx;
    *(float4*)(base + 256) = mn;
    *(float4*)(base + 384) = sd;
}

__global__ __launch_bounds__(256) void k_agg(const int* __restrict__ cols,
                                             const float* __restrict__ vA,
                                             const float* __restrict__ vC, int N) {
    int warp = (blockIdx.x * blockDim.x + threadIdx.x) >> 5;
    int lane = threadIdx.x & 31;
    if (warp >= N) return;
    const int r0 = g_rowptr[warp], r1 = g_rowptr[warp + 1];

    const float NEG = -CUDART_INF_F, POS = CUDART_INF_F;
    float4 s1 = {0, 0, 0, 0}, q1 = {0, 0, 0, 0};
    float4 s2 = {0, 0, 0, 0}, q2 = {0, 0, 0, 0};
    float4 s3 = {0, 0, 0, 0}, q3 = {0, 0, 0, 0};
    float4 x1 = {NEG, NEG, NEG, NEG}, n1 = {POS, POS, POS, POS};
    float4 x2 = x1, n2 = n1, x3 = x1, n3 = n1;

    for (int e = r0; e < r1; e++) {
        int c = __ldg(cols + e);
        float a = __ldg(vA + e);
        float b = __ldg(vC + e);
        float h = a * b;
        const float* p = g_m + (size_t)c * 384 + lane * 4;
        float4 v1 = *(const float4*)(p);
        float4 v2 = *(const float4*)(p + 128);
        float4 v3 = *(const float4*)(p + 256);
        agg_upd(v1, a, s1, q1, x1, n1);
        agg_upd(v2, b, s2, q2, x2, n2);
        agg_upd(v3, h, s3, q3, x3, n3);
    }
    const int deg = r1 - r0;
    const float inv = 1.f / fmaxf((float)deg, 1.f);
    float* fb = g_feats + (size_t)warp * 1536 + lane * 4;
    agg_finish(deg, inv, s1, q1, x1, n1, fb);
    agg_finish(deg, inv, s2, q2, x2, n2, fb + 512);
    agg_finish(deg, inv, s3, q3, x3, n3, fb + 1024);
}

// ---------------- output GEMM (tf32 tensor cores, 3-stage cp.async ring) ----------------
// out = feats[N,1536] @ pw[1536,128] + sum(pna_b). 128x128 block tile, 8 warps
// (2x4), 64x32 warp tiles of m16n8k8 tf32 MMAs, rna-rounded fragments.
#define APAD 20
#define BPAD 132
#define AST (128 * APAD)          // floats per As stage
#define BST (16 * BPAD)           // floats per Bs stage
#define KOUT_SMEM ((3 * AST + 3 * BST) * 4)

__global__ __launch_bounds__(256, 2) void k_out(const float* __restrict__ pw,
                                                const float* __restrict__ pb,
                                                float* __restrict__ out, int N) {
    extern __shared__ __align__(16) float sm[];
    float* Asb = sm;                 // [3][128][APAD]
    float* Bsb = sm + 3 * AST;       // [3][16][BPAD]

    const int bm = blockIdx.x * 128;
    const int tid = threadIdx.x;
    const int lane = tid & 31;
    const int wid = tid >> 5;
    const int wm = wid >> 2;          // 0..1 : 64 rows
    const int wn = wid & 3;           // 0..3 : 32 cols
    const int tq = lane >> 2;         // 0..7
    const int tr = lane & 3;          // 0..3

    // staging mapping
    const int ar0  = tid >> 2;        // 0..63
    const int akq  = (tid & 3) << 2;  // 0,4,8,12
    const int bkk0 = tid >> 5;        // 0..7
    const int bjq  = (tid & 31) << 2; // 0..124

    int gr0 = bm + ar0;      if (gr0 >= N) gr0 = N - 1;
    int gr1 = bm + ar0 + 64; if (gr1 >= N) gr1 = N - 1;
    const float* sA0 = g_feats + (size_t)gr0 * 1536 + akq;
    const float* sA1 = g_feats + (size_t)gr1 * 1536 + akq;
    const float* sB0 = pw + (size_t)bkk0 * 128 + bjq;
    const float* sB1 = pw + (size_t)(bkk0 + 8) * 128 + bjq;

    const unsigned dA0 = (unsigned)__cvta_generic_to_shared(&Asb[ar0 * APAD + akq]);
    const unsigned dA1 = (unsigned)__cvta_generic_to_shared(&Asb[(ar0 + 64) * APAD + akq]);
    const unsigned dB0 = (unsigned)__cvta_generic_to_shared(&Bsb[bkk0 * BPAD + bjq]);
    const unsigned dB1 = (unsigned)__cvta_generic_to_shared(&Bsb[(bkk0 + 8) * BPAD + bjq]);

    const int NK = 96;  // k16 chunks
#pragma unroll
    for (int p = 0; p < 2; p++) {  // preload stages 0,1
        cpasync16(dA0 + p * AST * 4, sA0 + p * 16);
        cpasync16(dA1 + p * AST * 4, sA1 + p * 16);
        cpasync16(dB0 + p * BST * 4, sB0 + (size_t)p * 2048);
        cpasync16(dB1 + p * BST * 4, sB1 + (size_t)p * 2048);
        cp_commit();
    }

    float acc[4][4][4] = {};  // [mt][nt][reg]

    for (int i = 0; i < NK; i++) {
        cp_wait1();
        __syncthreads();
        // issue chunk i+2 into slot (i+2)%3 — last read at iteration i-1, safe past the barrier
        const int nc = i + 2;
        if (nc < NK) {
            const int sl = nc - (nc / 3) * 3;
            cpasync16(dA0 + sl * AST * 4, sA0 + nc * 16);
            cpasync16(dA1 + sl * AST * 4, sA1 + nc * 16);
            cpasync16(dB0 + sl * BST * 4, sB0 + (size_t)nc * 2048);
            cpasync16(dB1 + sl * BST * 4, sB1 + (size_t)nc * 2048);
        }
        cp_commit();

        const int buf = i - (i / 3) * 3;
        const float* A = Asb + buf * AST;
        const float* B = Bsb + buf * BST;
#pragma unroll
        for (int s = 0; s < 2; s++) {  // two k8 steps per chunk
            unsigned afr[4][4], bfr[4][2];
#pragma unroll
            for (int mt = 0; mt < 4; mt++) {
                const int r = wm * 64 + mt * 16 + tq;
                const int c = s * 8 + tr;
                afr[mt][0] = f2tf32(A[r * APAD + c]);
                afr[mt][1] = f2tf32(A[(r + 8) * APAD + c]);
                afr[mt][2] = f2tf32(A[r * APAD + c + 4]);
                afr[mt][3] = f2tf32(A[(r + 8) * APAD + c + 4]);
            }
#pragma unroll
            for (int nt = 0; nt < 4; nt++) {
                const int c = wn * 32 + nt * 8 + tq;
                bfr[nt][0] = f2tf32(B[(s * 8 + tr) * BPAD + c]);
                bfr[nt][1] = f2tf32(B[(s * 8 + tr + 4) * BPAD + c]);
            }
#pragma unroll
            for (int mt = 0; mt < 4; mt++)
#pragma unroll
                for (int nt = 0; nt < 4; nt++)
                    mma_tf32(acc[mt][nt], afr[mt], bfr[nt]);
        }
    }

    // epilogue: bias = sum of 3 bias rows; each thread owns 2x2 per (mt,nt) tile
#pragma unroll
    for (int nt = 0; nt < 4; nt++) {
        const int c0 = wn * 32 + nt * 8 + 2 * tr;
        const float b0 = __ldg(pb + c0) + __ldg(pb + 128 + c0) + __ldg(pb + 256 + c0);
        const float b1 = __ldg(pb + c0 + 1) + __ldg(pb + 128 + c0 + 1) + __ldg(pb + 256 + c0 + 1);
#pragma unroll
        for (int mt = 0; mt < 4; mt++) {
            const int r0 = bm + wm * 64 + mt * 16 + tq;
            if (r0 < N) {
                float2 v = make_float2(acc[mt][nt][0] + b0, acc[mt][nt][1] + b1);
                *(float2*)&out[(size_t)r0 * 128 + c0] = v;
            }
            const int r1 = r0 + 8;
            if (r1 < N) {
                float2 v = make_float2(acc[mt][nt][2] + b0, acc[mt][nt][3] + b1);
                *(float2*)&out[(size_t)r1 * 128 + c0] = v;
            }
        }
    }
}

// ---------------- launch ----------------
extern "C" void kernel_launch(void* const* d_in, const int* in_sizes, int n_in,
                              void* d_out, int out_size) {
    const float* x    = (const float*)d_in[0];
    const int*   rows = (const int*)d_in[1];
    const int*   cols = (const int*)d_in[2];
    const float* vA   = (const float*)d_in[3];
    const float* vC   = (const float*)d_in[4];
    const float* W    = (const float*)d_in[5];
    const float* W2   = (const float*)d_in[6];
    const float* W3   = (const float*)d_in[7];
    const float* pw   = (const float*)d_in[8];  // [3,512,128] == flat [1536,128]
    const float* pb   = (const float*)d_in[9];  // [3,128]
    float* out = (float*)d_out;

    const int N = in_sizes[0] / 128;
    const int E = in_sizes[1];

    // idempotent, not stream-ordered; safe under graph capture
    cudaFuncSetAttribute(k_out, cudaFuncAttributeMaxDynamicSharedMemorySize, KOUT_SMEM);

    k_rowptr<<<(N + 1 + 255) / 256, 256>>>(rows, E, N);
    dim3 gproj((N + 127) / 128, 3);
    k_proj<<<gproj, 256>>>(x, W, W2, W3, N);
    k_agg<<<(N + 7) / 8, 256>>>(cols, vA, vC, N);
    k_out<<<(N + 127) / 128, 256, KOUT_SMEM>>>(pw, pb, out, N);
}

// round 8
// speedup vs baseline: 1.2004x; 1.2004x over previous
#include <cuda_runtime.h>
#include <math_constants.h>
#include <cstdint>

#define NNODES 100000
#define NEDGES 1600000

// ---------------- scratch (static __device__ — no allocs allowed) ----------------
__device__ float g_m[(size_t)NNODES * 384];       // projected messages [N][3*128]
__device__ float g_feats[(size_t)NNODES * 1536];  // PNA features, tf32-rounded
__device__ int   g_rowptr[NNODES + 1];
__device__ float g_xr[(size_t)NNODES * 128];      // x, tf32-rounded
__device__ float g_wr[3 * 128 * 128];             // W|W2|W3, tf32-rounded
__device__ float g_pwr[1536 * 128];               // pna_w flat, tf32-rounded

// ---------------- cp.async helpers ----------------
__device__ __forceinline__ void cpasync16(unsigned int dst, const float* src) {
    asm volatile("cp.async.cg.shared.global [%0], [%1], 16;\n" :: "r"(dst), "l"(src));
}
__device__ __forceinline__ void cp_commit() {
    asm volatile("cp.async.commit_group;\n" ::);
}
__device__ __forceinline__ void cp_wait1() {
    asm volatile("cp.async.wait_group 1;\n" ::);
}

// ---------------- tf32 helpers ----------------
__device__ __forceinline__ unsigned f2tf32(float f) {
    unsigned r;
    asm("cvt.rna.tf32.f32 %0, %1;" : "=r"(r) : "f"(f));
    return r;
}
__device__ __forceinline__ float rnd1(float f) { return __uint_as_float(f2tf32(f)); }
__device__ __forceinline__ float4 rnd4(float4 v) {
    return make_float4(rnd1(v.x), rnd1(v.y), rnd1(v.z), rnd1(v.w));
}
__device__ __forceinline__ void mma_tf32(float* d, const unsigned* a, const unsigned* b) {
    asm volatile(
        "mma.sync.aligned.m16n8k8.row.col.f32.tf32.tf32.f32 "
        "{%0,%1,%2,%3},{%4,%5,%6,%7},{%8,%9},{%0,%1,%2,%3};\n"
        : "+f"(d[0]), "+f"(d[1]), "+f"(d[2]), "+f"(d[3])
        : "r"(a[0]), "r"(a[1]), "r"(a[2]), "r"(a[3]), "r"(b[0]), "r"(b[1]));
}

// ---------------- tf32 pre-rounding pass ----------------
__global__ void k_round(const float* __restrict__ src, float* __restrict__ dst, int n4) {
    int i = blockIdx.x * blockDim.x + threadIdx.x;
    if (i < n4) {
        float4 v = *(const float4*)&src[i * 4];
        *(float4*)&dst[i * 4] = rnd4(v);
    }
}

// ---------------- row pointers from sorted rows ----------------
__global__ void k_rowptr(const int* __restrict__ rows, int E, int N) {
    int i = blockIdx.x * blockDim.x + threadIdx.x;
    if (i > N) return;
    int lo = 0, hi = E;
    while (lo < hi) {
        int mid = (lo + hi) >> 1;
        if (__ldg(rows + mid) < i) lo = mid + 1; else hi = mid;
    }
    g_rowptr[i] = lo;
}

// =====================================================================
// tf32 MMA GEMM core (shared by k_proj and k_out): 128x128 block tile,
// 8 warps (2x4), 64x32 warp tiles, m16n8k8, 3-stage cp.async ring.
// A [N,KTOT] row-major (pre-rounded), B [KTOT,128] (pre-rounded).
// =====================================================================
#define APAD 20
#define BPAD 132
#define AST (128 * APAD)
#define BST (16 * BPAD)
#define GEMM_SMEM ((3 * AST + 3 * BST) * 4)

template <int KTOT>
__device__ __forceinline__ void gemm_tf32_core(
    const float* __restrict__ Aglob, int lda,   // A base (block rows applied), stride lda
    const float* __restrict__ Bglob,            // B base [KTOT,128]
    float acc[4][4][4], int bm, int N, float* sm) {
    float* Asb = sm;
    float* Bsb = sm + 3 * AST;

    const int tid = threadIdx.x;
    const int lane = tid & 31;
    const int wid = tid >> 5;
    const int wm = wid >> 2, wn = wid & 3;
    const int tq = lane >> 2, tr = lane & 3;

    const int ar0  = tid >> 2;
    const int akq  = (tid & 3) << 2;
    const int bkk0 = tid >> 5;
    const int bjq  = (tid & 31) << 2;

    int gr0 = bm + ar0;      if (gr0 >= N) gr0 = N - 1;
    int gr1 = bm + ar0 + 64; if (gr1 >= N) gr1 = N - 1;
    const float* sA0 = Aglob + (size_t)gr0 * lda + akq;
    const float* sA1 = Aglob + (size_t)gr1 * lda + akq;
    const float* sB0 = Bglob + (size_t)bkk0 * 128 + bjq;
    const float* sB1 = Bglob + (size_t)(bkk0 + 8) * 128 + bjq;

    const unsigned dA0 = (unsigned)__cvta_generic_to_shared(&Asb[ar0 * APAD + akq]);
    const unsigned dA1 = (unsigned)__cvta_generic_to_shared(&Asb[(ar0 + 64) * APAD + akq]);
    const unsigned dB0 = (unsigned)__cvta_generic_to_shared(&Bsb[bkk0 * BPAD + bjq]);
    const unsigned dB1 = (unsigned)__cvta_generic_to_shared(&Bsb[(bkk0 + 8) * BPAD + bjq]);

    const int NK = KTOT / 16;
#pragma unroll
    for (int p = 0; p < 2; p++) {
        cpasync16(dA0 + p * AST * 4, sA0 + p * 16);
        cpasync16(dA1 + p * AST * 4, sA1 + p * 16);
        cpasync16(dB0 + p * BST * 4, sB0 + (size_t)p * 2048);
        cpasync16(dB1 + p * BST * 4, sB1 + (size_t)p * 2048);
        cp_commit();
    }

    for (int i = 0; i < NK; i++) {
        cp_wait1();
        __syncthreads();
        const int nc = i + 2;
        if (nc < NK) {
            const int sl = nc - (nc / 3) * 3;
            cpasync16(dA0 + sl * AST * 4, sA0 + nc * 16);
            cpasync16(dA1 + sl * AST * 4, sA1 + nc * 16);
            cpasync16(dB0 + sl * BST * 4, sB0 + (size_t)nc * 2048);
            cpasync16(dB1 + sl * BST * 4, sB1 + (size_t)nc * 2048);
        }
        cp_commit();

        const int buf = i - (i / 3) * 3;
        const float* A = Asb + buf * AST;
        const float* B = Bsb + buf * BST;
#pragma unroll
        for (int s = 0; s < 2; s++) {
            unsigned afr[4][4], bfr[4][2];
#pragma unroll
            for (int mt = 0; mt < 4; mt++) {
                const int r = wm * 64 + mt * 16 + tq;
                const int c = s * 8 + tr;
                afr[mt][0] = __float_as_uint(A[r * APAD + c]);
                afr[mt][1] = __float_as_uint(A[(r + 8) * APAD + c]);
                afr[mt][2] = __float_as_uint(A[r * APAD + c + 4]);
                afr[mt][3] = __float_as_uint(A[(r + 8) * APAD + c + 4]);
            }
#pragma unroll
            for (int nt = 0; nt < 4; nt++) {
                const int c = wn * 32 + nt * 8 + tq;
                bfr[nt][0] = __float_as_uint(B[(s * 8 + tr) * BPAD + c]);
                bfr[nt][1] = __float_as_uint(B[(s * 8 + tr + 4) * BPAD + c]);
            }
#pragma unroll
            for (int mt = 0; mt < 4; mt++)
#pragma unroll
                for (int nt = 0; nt < 4; nt++)
                    mma_tf32(acc[mt][nt], afr[mt], bfr[nt]);
        }
    }
}

// ---------------- projection GEMM (tf32): g_m[:,slab*128+..] = xr @ wr[slab] ----------------
__global__ __launch_bounds__(256, 2) void k_proj(int N) {
    extern __shared__ __align__(16) float sm[];
    const int bm = blockIdx.x * 128;
    const int slab = blockIdx.y;
    float acc[4][4][4] = {};
    gemm_tf32_core<128>(g_xr, 128, g_wr + slab * 128 * 128, acc, bm, N, sm);

    const int lane = threadIdx.x & 31;
    const int wid = threadIdx.x >> 5;
    const int wm = wid >> 2, wn = wid & 3;
    const int tq = lane >> 2, tr = lane & 3;
#pragma unroll
    for (int nt = 0; nt < 4; nt++) {
        const int c0 = slab * 128 + wn * 32 + nt * 8 + 2 * tr;
#pragma unroll
        for (int mt = 0; mt < 4; mt++) {
            const int r0 = bm + wm * 64 + mt * 16 + tq;
            if (r0 < N) {
                float2 v = make_float2(acc[mt][nt][0], acc[mt][nt][1]);
                *(float2*)&g_m[(size_t)r0 * 384 + c0] = v;
            }
            const int r1 = r0 + 8;
            if (r1 < N) {
                float2 v = make_float2(acc[mt][nt][2], acc[mt][nt][3]);
                *(float2*)&g_m[(size_t)r1 * 384 + c0] = v;
            }
        }
    }
}

// ---------------- aggregation: warp-per-node segment mean/max/min/std ----------------
__device__ __forceinline__ void agg_upd(float4 v, float s, float4& su, float4& sq,
                                        float4& mx, float4& mn) {
    float gx = v.x * s, gy = v.y * s, gz = v.z * s, gw = v.w * s;
    su.x += gx; su.y += gy; su.z += gz; su.w += gw;
    sq.x += gx * gx; sq.y += gy * gy; sq.z += gz * gz; sq.w += gw * gw;
    mx.x = fmaxf(mx.x, gx); mx.y = fmaxf(mx.y, gy); mx.z = fmaxf(mx.z, gz); mx.w = fmaxf(mx.w, gw);
    mn.x = fminf(mn.x, gx); mn.y = fminf(mn.y, gy); mn.z = fminf(mn.z, gz); mn.w = fminf(mn.w, gw);
}

__device__ __forceinline__ void agg_finish(int deg, float inv, float4 su, float4 sq,
                                           float4 mx, float4 mn, float* base) {
    float4 mean, var, sd;
    mean.x = su.x * inv; mean.y = su.y * inv; mean.z = su.z * inv; mean.w = su.w * inv;
    var.x = fmaxf(sq.x * inv - mean.x * mean.x, 0.f);
    var.y = fmaxf(sq.y * inv - mean.y * mean.y, 0.f);
    var.z = fmaxf(sq.z * inv - mean.z * mean.z, 0.f);
    var.w = fmaxf(sq.w * inv - mean.w * mean.w, 0.f);
    sd.x = sqrtf(var.x + 1e-5f); sd.y = sqrtf(var.y + 1e-5f);
    sd.z = sqrtf(var.z + 1e-5f); sd.w = sqrtf(var.w + 1e-5f);
    if (deg == 0) {
        mx = make_float4(0.f, 0.f, 0.f, 0.f);
        mn = make_float4(0.f, 0.f, 0.f, 0.f);
    }
    // tf32-round at store so k_out can feed raw bits to MMA
    *(float4*)(base)       = rnd4(mean);
    *(float4*)(base + 128) = rnd4(mx);
    *(float4*)(base + 256) = rnd4(mn);
    *(float4*)(base + 384) = rnd4(sd);
}

__global__ __launch_bounds__(256) void k_agg(const int* __restrict__ cols,
                                             const float* __restrict__ vA,
                                             const float* __restrict__ vC, int N) {
    int warp = (blockIdx.x * blockDim.x + threadIdx.x) >> 5;
    int lane = threadIdx.x & 31;
    if (warp >= N) return;
    const int r0 = g_rowptr[warp], r1 = g_rowptr[warp + 1];

    const float NEG = -CUDART_INF_F, POS = CUDART_INF_F;
    float4 s1 = {0, 0, 0, 0}, q1 = {0, 0, 0, 0};
    float4 s2 = {0, 0, 0, 0}, q2 = {0, 0, 0, 0};
    float4 s3 = {0, 0, 0, 0}, q3 = {0, 0, 0, 0};
    float4 x1 = {NEG, NEG, NEG, NEG}, n1 = {POS, POS, POS, POS};
    float4 x2 = x1, n2 = n1, x3 = x1, n3 = n1;

    int e = r0;
    for (; e + 2 <= r1; e += 2) {  // 2-edge unroll: double load MLP
        int ca = __ldg(cols + e), cb = __ldg(cols + e + 1);
        float aa = __ldg(vA + e), ab = __ldg(vA + e + 1);
        float ba = __ldg(vC + e), bb = __ldg(vC + e + 1);
        const float* pa = g_m + (size_t)ca * 384 + lane * 4;
        const float* pb2 = g_m + (size_t)cb * 384 + lane * 4;
        float4 u1 = *(const float4*)(pa);
        float4 u2 = *(const float4*)(pa + 128);
        float4 u3 = *(const float4*)(pa + 256);
        float4 w1 = *(const float4*)(pb2);
        float4 w2 = *(const float4*)(pb2 + 128);
        float4 w3 = *(const float4*)(pb2 + 256);
        agg_upd(u1, aa, s1, q1, x1, n1);
        agg_upd(u2, ba, s2, q2, x2, n2);
        agg_upd(u3, aa * ba, s3, q3, x3, n3);
        agg_upd(w1, ab, s1, q1, x1, n1);
        agg_upd(w2, bb, s2, q2, x2, n2);
        agg_upd(w3, ab * bb, s3, q3, x3, n3);
    }
    for (; e < r1; e++) {
        int c = __ldg(cols + e);
        float a = __ldg(vA + e);
        float b = __ldg(vC + e);
        const float* p = g_m + (size_t)c * 384 + lane * 4;
        float4 v1 = *(const float4*)(p);
        float4 v2 = *(const float4*)(p + 128);
        float4 v3 = *(const float4*)(p + 256);
        agg_upd(v1, a, s1, q1, x1, n1);
        agg_upd(v2, b, s2, q2, x2, n2);
        agg_upd(v3, a * b, s3, q3, x3, n3);
    }
    const int deg = r1 - r0;
    const float inv = 1.f / fmaxf((float)deg, 1.f);
    float* fb = g_feats + (size_t)warp * 1536 + lane * 4;
    agg_finish(deg, inv, s1, q1, x1, n1, fb);
    agg_finish(deg, inv, s2, q2, x2, n2, fb + 512);
    agg_finish(deg, inv, s3, q3, x3, n3, fb + 1024);
}

// ---------------- output GEMM (tf32): out = feats @ pwr + sum(pna_b) ----------------
__global__ __launch_bounds__(256, 2) void k_out(const float* __restrict__ pb,
                                                float* __restrict__ out, int N) {
    extern __shared__ __align__(16) float sm[];
    const int bm = blockIdx.x * 128;
    float acc[4][4][4] = {};
    gemm_tf32_core<1536>(g_feats, 1536, g_pwr, acc, bm, N, sm);

    const int lane = threadIdx.x & 31;
    const int wid = threadIdx.x >> 5;
    const int wm = wid >> 2, wn = wid & 3;
    const int tq = lane >> 2, tr = lane & 3;
#pragma unroll
    for (int nt = 0; nt < 4; nt++) {
        const int c0 = wn * 32 + nt * 8 + 2 * tr;
        const float b0 = __ldg(pb + c0) + __ldg(pb + 128 + c0) + __ldg(pb + 256 + c0);
        const float b1 = __ldg(pb + c0 + 1) + __ldg(pb + 128 + c0 + 1) + __ldg(pb + 256 + c0 + 1);
#pragma unroll
        for (int mt = 0; mt < 4; mt++) {
            const int r0 = bm + wm * 64 + mt * 16 + tq;
            if (r0 < N) {
                float2 v = make_float2(acc[mt][nt][0] + b0, acc[mt][nt][1] + b1);
                *(float2*)&out[(size_t)r0 * 128 + c0] = v;
            }
            const int r1 = r0 + 8;
            if (r1 < N) {
                float2 v = make_float2(acc[mt][nt][2] + b0, acc[mt][nt][3] + b1);
                *(float2*)&out[(size_t)r1 * 128 + c0] = v;
            }
        }
    }
}

// ---------------- launch ----------------
extern "C" void kernel_launch(void* const* d_in, const int* in_sizes, int n_in,
                              void* d_out, int out_size) {
    const float* x    = (const float*)d_in[0];
    const int*   rows = (const int*)d_in[1];
    const int*   cols = (const int*)d_in[2];
    const float* vA   = (const float*)d_in[3];
    const float* vC   = (const float*)d_in[4];
    const float* W    = (const float*)d_in[5];
    const float* W2   = (const float*)d_in[6];
    const float* W3   = (const float*)d_in[7];
    const float* pw   = (const float*)d_in[8];  // [3,512,128] == flat [1536,128]
    const float* pb   = (const float*)d_in[9];  // [3,128]
    float* out = (float*)d_out;

    const int N = in_sizes[0] / 128;
    const int E = in_sizes[1];

    // idempotent, not stream-ordered; safe under graph capture
    cudaFuncSetAttribute(k_proj, cudaFuncAttributeMaxDynamicSharedMemorySize, GEMM_SMEM);
    cudaFuncSetAttribute(k_out,  cudaFuncAttributeMaxDynamicSharedMemorySize, GEMM_SMEM);

    float* wr_dev;  cudaGetSymbolAddress((void**)&wr_dev, g_wr);
    float* xr_dev;  cudaGetSymbolAddress((void**)&xr_dev, g_xr);
    float* pwr_dev; cudaGetSymbolAddress((void**)&pwr_dev, g_pwr);

    k_rowptr<<<(N + 1 + 255) / 256, 256>>>(rows, E, N);

    // tf32 pre-rounding
    const int nx4 = (N * 128) / 4;
    k_round<<<(nx4 + 255) / 256, 256>>>(x, xr_dev, nx4);
    k_round<<<(16384 / 4 + 255) / 256, 256>>>(W,  wr_dev,             16384 / 4);
    k_round<<<(16384 / 4 + 255) / 256, 256>>>(W2, wr_dev + 16384,     16384 / 4);
    k_round<<<(16384 / 4 + 255) / 256, 256>>>(W3, wr_dev + 32768,     16384 / 4);
    k_round<<<(196608 / 4 + 255) / 256, 256>>>(pw, pwr_dev,           196608 / 4);

    dim3 gproj((N + 127) / 128, 3);
    k_proj<<<gproj, 256, GEMM_SMEM>>>(N);
    k_agg<<<(N + 7) / 8, 256>>>(cols, vA, vC, N);
    k_out<<<(N + 127) / 128, 256, GEMM_SMEM>>>(pb, out, N);
}

// round 9
// speedup vs baseline: 1.6235x; 1.3525x over previous
#include <cuda_runtime.h>
#include <cuda_fp16.h>
#include <math_constants.h>
#include <cstdint>

#define NNODES 100000
#define NEDGES 1600000

// ---------------- scratch (static __device__ — no allocs allowed) ----------------
__device__ __half g_mh[(size_t)NNODES * 384];     // projected messages, fp16 [N][3*128]
__device__ __half g_fh[(size_t)NNODES * 1536];    // PNA features, fp16 [N][1536]
__device__ __half g_xh[(size_t)NNODES * 128];     // x, fp16
__device__ __half g_wh[3 * 128 * 128];            // W|W2|W3 TRANSPOSED [n][k], fp16
__device__ __half g_pwh[128 * 1536];              // pna_w TRANSPOSED [n=128][k=1536], fp16
__device__ int    g_rowptr[NNODES + 1];

// ---------------- cp.async helpers ----------------
__device__ __forceinline__ void cpasync16(unsigned int dst, const void* src) {
    asm volatile("cp.async.cg.shared.global [%0], [%1], 16;\n" :: "r"(dst), "l"(src));
}
__device__ __forceinline__ void cp_commit() {
    asm volatile("cp.async.commit_group;\n" ::);
}
__device__ __forceinline__ void cp_wait1() {
    asm volatile("cp.async.wait_group 1;\n" ::);
}

// ---------------- fp16 MMA m16n8k16 ----------------
__device__ __forceinline__ void mma_f16(float* d, const unsigned* a, const unsigned* b) {
    asm volatile(
        "mma.sync.aligned.m16n8k16.row.col.f32.f16.f16.f32 "
        "{%0,%1,%2,%3},{%4,%5,%6,%7},{%8,%9},{%0,%1,%2,%3};\n"
        : "+f"(d[0]), "+f"(d[1]), "+f"(d[2]), "+f"(d[3])
        : "r"(a[0]), "r"(a[1]), "r"(a[2]), "r"(a[3]), "r"(b[0]), "r"(b[1]));
}

// ---------------- conversion kernels ----------------
__global__ void k_cvt_x(const float* __restrict__ src, __half* __restrict__ dst, int n4) {
    int i = blockIdx.x * blockDim.x + threadIdx.x;
    if (i < n4) {
        float4 v = *(const float4*)&src[i * 4];
        __half2 h0 = __floats2half2_rn(v.x, v.y);
        __half2 h1 = __floats2half2_rn(v.z, v.w);
        uint2 o;
        o.x = *(unsigned*)&h0;
        o.y = *(unsigned*)&h1;
        *(uint2*)&dst[i * 4] = o;
    }
}

// transpose + convert: src [K][Ncols] fp32 -> dst [Ncols][K] fp16
__global__ void k_cvt_t(const float* __restrict__ src, __half* __restrict__ dst,
                        int K, int Ncols) {
    int i = blockIdx.x * blockDim.x + threadIdx.x;
    if (i < K * Ncols) {
        int k = i / Ncols, n = i % Ncols;
        dst[(size_t)n * K + k] = __float2half_rn(src[i]);
    }
}

// ---------------- row pointers from sorted rows ----------------
__global__ void k_rowptr(const int* __restrict__ rows, int E, int N) {
    int i = blockIdx.x * blockDim.x + threadIdx.x;
    if (i > N) return;
    int lo = 0, hi = E;
    while (lo < hi) {
        int mid = (lo + hi) >> 1;
        if (__ldg(rows + mid) < i) lo = mid + 1; else hi = mid;
    }
    g_rowptr[i] = lo;
}

// =====================================================================
// fp16 MMA GEMM core: 128x128 block tile, 8 warps (2x4), 64x32 warp
// tiles of m16n8k16, 3-stage cp.async ring.
// A [N,LDA] row-major fp16.  B TRANSPOSED [128,LDB] row-major fp16
// (row n, col k).  k chunk = 16.
// =====================================================================
#define APADH 24                        // halves per smem row (16 data + 8 pad = 48B)
#define STH   (128 * APADH)             // halves per stage (A or B)
#define GEMM_SMEM (6 * STH * 2)         // 3 stages A + 3 stages B, bytes (36 KB)

template <int NK, int LDA, int LDB>
__device__ __forceinline__ void gemm_fp16_core(
    const __half* __restrict__ Ag, const __half* __restrict__ Bg,
    float acc[4][4][4], int bm, int N, __half* sm) {
    __half* Asb = sm;                // [3][128][APADH]
    __half* Bsb = sm + 3 * STH;      // [3][128][APADH]

    const int tid = threadIdx.x;
    const int lane = tid & 31;
    const int wid = tid >> 5;
    const int wm = wid >> 2, wn = wid & 3;
    const int tq = lane >> 2, tr = lane & 3;

    // staging: thread -> (row, 16B-half-chunk)
    const int srow = tid >> 1;             // 0..127
    const int shalf = (tid & 1) * 8;       // 0 or 8 halves

    int gr = bm + srow; if (gr >= N) gr = N - 1;
    const __half* sA = Ag + (size_t)gr * LDA + shalf;
    const __half* sB = Bg + (size_t)srow * LDB + shalf;

    const unsigned dA = (unsigned)__cvta_generic_to_shared(&Asb[srow * APADH + shalf]);
    const unsigned dB = (unsigned)__cvta_generic_to_shared(&Bsb[srow * APADH + shalf]);

#pragma unroll
    for (int p = 0; p < 2; p++) {   // preload stages 0,1
        cpasync16(dA + p * STH * 2, sA + p * 16);
        cpasync16(dB + p * STH * 2, sB + p * 16);
        cp_commit();
    }

    for (int i = 0; i < NK; i++) {
        cp_wait1();
        __syncthreads();
        const int nc = i + 2;
        if (nc < NK) {
            const int sl = nc - (nc / 3) * 3;
            cpasync16(dA + sl * STH * 2, sA + nc * 16);
            cpasync16(dB + sl * STH * 2, sB + nc * 16);
        }
        cp_commit();

        const int buf = i - (i / 3) * 3;
        const __half* A = Asb + buf * STH;
        const __half* B = Bsb + buf * STH;

        unsigned afr[4][4], bfr[4][2];
#pragma unroll
        for (int mt = 0; mt < 4; mt++) {
            const int r = wm * 64 + mt * 16 + tq;
            afr[mt][0] = *(const unsigned*)&A[r * APADH + 2 * tr];
            afr[mt][1] = *(const unsigned*)&A[(r + 8) * APADH + 2 * tr];
            afr[mt][2] = *(const unsigned*)&A[r * APADH + 2 * tr + 8];
            afr[mt][3] = *(const unsigned*)&A[(r + 8) * APADH + 2 * tr + 8];
        }
#pragma unroll
        for (int nt = 0; nt < 4; nt++) {
            const int nq = wn * 32 + nt * 8 + tq;
            bfr[nt][0] = *(const unsigned*)&B[nq * APADH + 2 * tr];
            bfr[nt][1] = *(const unsigned*)&B[nq * APADH + 2 * tr + 8];
        }
#pragma unroll
        for (int mt = 0; mt < 4; mt++)
#pragma unroll
            for (int nt = 0; nt < 4; nt++)
                mma_f16(acc[mt][nt], afr[mt], bfr[nt]);
    }
}

// ---------------- projection GEMM (fp16 MMA): g_mh[:,slab*128+..] = xh @ W[slab] ----------------
__global__ __launch_bounds__(256, 2) void k_proj(int N) {
    extern __shared__ __align__(16) __half smh[];
    const int bm = blockIdx.x * 128;
    const int slab = blockIdx.y;
    float acc[4][4][4] = {};
    gemm_fp16_core<8, 128, 128>(g_xh, g_wh + slab * 128 * 128, acc, bm, N, smh);

    const int lane = threadIdx.x & 31;
    const int wid = threadIdx.x >> 5;
    const int wm = wid >> 2, wn = wid & 3;
    const int tq = lane >> 2, tr = lane & 3;
#pragma unroll
    for (int nt = 0; nt < 4; nt++) {
        const int c0 = slab * 128 + wn * 32 + nt * 8 + 2 * tr;
#pragma unroll
        for (int mt = 0; mt < 4; mt++) {
            const int r0 = bm + wm * 64 + mt * 16 + tq;
            if (r0 < N) {
                __half2 h = __floats2half2_rn(acc[mt][nt][0], acc[mt][nt][1]);
                *(__half2*)&g_mh[(size_t)r0 * 384 + c0] = h;
            }
            const int r1 = r0 + 8;
            if (r1 < N) {
                __half2 h = __floats2half2_rn(acc[mt][nt][2], acc[mt][nt][3]);
                *(__half2*)&g_mh[(size_t)r1 * 384 + c0] = h;
            }
        }
    }
}

// ---------------- aggregation: warp-per-node segment mean/max/min/std ----------------
__device__ __forceinline__ float4 h4tof4(uint2 u) {
    __half2 a = *(__half2*)&u.x;
    __half2 b = *(__half2*)&u.y;
    float2 fa = __half22float2(a), fb = __half22float2(b);
    return make_float4(fa.x, fa.y, fb.x, fb.y);
}

__device__ __forceinline__ void agg_upd(float4 v, float s, float4& su, float4& sq,
                                        float4& mx, float4& mn) {
    float gx = v.x * s, gy = v.y * s, gz = v.z * s, gw = v.w * s;
    su.x += gx; su.y += gy; su.z += gz; su.w += gw;
    sq.x += gx * gx; sq.y += gy * gy; sq.z += gz * gz; sq.w += gw * gw;
    mx.x = fmaxf(mx.x, gx); mx.y = fmaxf(mx.y, gy); mx.z = fmaxf(mx.z, gz); mx.w = fmaxf(mx.w, gw);
    mn.x = fminf(mn.x, gx); mn.y = fminf(mn.y, gy); mn.z = fminf(mn.z, gz); mn.w = fminf(mn.w, gw);
}

__device__ __forceinline__ void sth4(__half* p, float4 v) {
    __half2 h0 = __floats2half2_rn(v.x, v.y);
    __half2 h1 = __floats2half2_rn(v.z, v.w);
    uint2 o; o.x = *(unsigned*)&h0; o.y = *(unsigned*)&h1;
    *(uint2*)p = o;
}

__device__ __forceinline__ void agg_finish(int deg, float inv, float4 su, float4 sq,
                                           float4 mx, float4 mn, __half* base) {
    float4 mean, var, sd;
    mean.x = su.x * inv; mean.y = su.y * inv; mean.z = su.z * inv; mean.w = su.w * inv;
    var.x = fmaxf(sq.x * inv - mean.x * mean.x, 0.f);
    var.y = fmaxf(sq.y * inv - mean.y * mean.y, 0.f);
    var.z = fmaxf(sq.z * inv - mean.z * mean.z, 0.f);
    var.w = fmaxf(sq.w * inv - mean.w * mean.w, 0.f);
    sd.x = sqrtf(var.x + 1e-5f); sd.y = sqrtf(var.y + 1e-5f);
    sd.z = sqrtf(var.z + 1e-5f); sd.w = sqrtf(var.w + 1e-5f);
    if (deg == 0) {
        mx = make_float4(0.f, 0.f, 0.f, 0.f);
        mn = make_float4(0.f, 0.f, 0.f, 0.f);
    }
    sth4(base,       mean);
    sth4(base + 128, mx);
    sth4(base + 256, mn);
    sth4(base + 384, sd);
}

__global__ __launch_bounds__(256) void k_agg(const int* __restrict__ cols,
                                             const float* __restrict__ vA,
                                             const float* __restrict__ vC, int N) {
    int warp = (blockIdx.x * blockDim.x + threadIdx.x) >> 5;
    int lane = threadIdx.x & 31;
    if (warp >= N) return;
    const int r0 = g_rowptr[warp], r1 = g_rowptr[warp + 1];

    const float NEG = -CUDART_INF_F, POS = CUDART_INF_F;
    float4 s1 = {0, 0, 0, 0}, q1 = {0, 0, 0, 0};
    float4 s2 = {0, 0, 0, 0}, q2 = {0, 0, 0, 0};
    float4 s3 = {0, 0, 0, 0}, q3 = {0, 0, 0, 0};
    float4 x1 = {NEG, NEG, NEG, NEG}, n1 = {POS, POS, POS, POS};
    float4 x2 = x1, n2 = n1, x3 = x1, n3 = n1;

    int e = r0;
    for (; e + 2 <= r1; e += 2) {  // 2-edge unroll for load MLP
        int ca = __ldg(cols + e), cb = __ldg(cols + e + 1);
        float aa = __ldg(vA + e), ab = __ldg(vA + e + 1);
        float ba = __ldg(vC + e), bb = __ldg(vC + e + 1);
        const __half* pa = g_mh + (size_t)ca * 384 + lane * 4;
        const __half* pbp = g_mh + (size_t)cb * 384 + lane * 4;
        uint2 u1 = __ldg((const uint2*)(pa));
        uint2 u2 = __ldg((const uint2*)(pa + 128));
        uint2 u3 = __ldg((const uint2*)(pa + 256));
        uint2 w1 = __ldg((const uint2*)(pbp));
        uint2 w2 = __ldg((const uint2*)(pbp + 128));
        uint2 w3 = __ldg((const uint2*)(pbp + 256));
        agg_upd(h4tof4(u1), aa, s1, q1, x1, n1);
        agg_upd(h4tof4(u2), ba, s2, q2, x2, n2);
        agg_upd(h4tof4(u3), aa * ba, s3, q3, x3, n3);
        agg_upd(h4tof4(w1), ab, s1, q1, x1, n1);
        agg_upd(h4tof4(w2), bb, s2, q2, x2, n2);
        agg_upd(h4tof4(w3), ab * bb, s3, q3, x3, n3);
    }
    for (; e < r1; e++) {
        int c = __ldg(cols + e);
        float a = __ldg(vA + e);
        float b = __ldg(vC + e);
        const __half* p = g_mh + (size_t)c * 384 + lane * 4;
        uint2 u1 = __ldg((const uint2*)(p));
        uint2 u2 = __ldg((const uint2*)(p + 128));
        uint2 u3 = __ldg((const uint2*)(p + 256));
        agg_upd(h4tof4(u1), a, s1, q1, x1, n1);
        agg_upd(h4tof4(u2), b, s2, q2, x2, n2);
        agg_upd(h4tof4(u3), a * b, s3, q3, x3, n3);
    }
    const int deg = r1 - r0;
    const float inv = 1.f / fmaxf((float)deg, 1.f);
    __half* fb = g_fh + (size_t)warp * 1536 + lane * 4;
    agg_finish(deg, inv, s1, q1, x1, n1, fb);
    agg_finish(deg, inv, s2, q2, x2, n2, fb + 512);
    agg_finish(deg, inv, s3, q3, x3, n3, fb + 1024);
}

// ---------------- output GEMM (fp16 MMA): out = feats @ pw + sum(pna_b) ----------------
__global__ __launch_bounds__(256, 2) void k_out(const float* __restrict__ pb,
                                                float* __restrict__ out, int N) {
    extern __shared__ __align__(16) __half smh[];
    const int bm = blockIdx.x * 128;
    float acc[4][4][4] = {};
    gemm_fp16_core<96, 1536, 1536>(g_fh, g_pwh, acc, bm, N, smh);

    const int lane = threadIdx.x & 31;
    const int wid = threadIdx.x >> 5;
    const int wm = wid >> 2, wn = wid & 3;
    const int tq = lane >> 2, tr = lane & 3;
#pragma unroll
    for (int nt = 0; nt < 4; nt++) {
        const int c0 = wn * 32 + nt * 8 + 2 * tr;
        const float b0 = __ldg(pb + c0) + __ldg(pb + 128 + c0) + __ldg(pb + 256 + c0);
        const float b1 = __ldg(pb + c0 + 1) + __ldg(pb + 128 + c0 + 1) + __ldg(pb + 256 + c0 + 1);
#pragma unroll
        for (int mt = 0; mt < 4; mt++) {
            const int r0 = bm + wm * 64 + mt * 16 + tq;
            if (r0 < N) {
                float2 v = make_float2(acc[mt][nt][0] + b0, acc[mt][nt][1] + b1);
                *(float2*)&out[(size_t)r0 * 128 + c0] = v;
            }
            const int r1 = r0 + 8;
            if (r1 < N) {
                float2 v = make_float2(acc[mt][nt][2] + b0, acc[mt][nt][3] + b1);
                *(float2*)&out[(size_t)r1 * 128 + c0] = v;
            }
        }
    }
}

// ---------------- launch ----------------
extern "C" void kernel_launch(void* const* d_in, const int* in_sizes, int n_in,
                              void* d_out, int out_size) {
    const float* x    = (const float*)d_in[0];
    const int*   rows = (const int*)d_in[1];
    const int*   cols = (const int*)d_in[2];
    const float* vA   = (const float*)d_in[3];
    const float* vC   = (const float*)d_in[4];
    const float* W    = (const float*)d_in[5];
    const float* W2   = (const float*)d_in[6];
    const float* W3   = (const float*)d_in[7];
    const float* pw   = (const float*)d_in[8];  // [3,512,128] == flat [1536,128]
    const float* pb   = (const float*)d_in[9];  // [3,128]
    float* out = (float*)d_out;

    const int N = in_sizes[0] / 128;
    const int E = in_sizes[1];

    // idempotent, not stream-ordered; safe under graph capture
    cudaFuncSetAttribute(k_proj, cudaFuncAttributeMaxDynamicSharedMemorySize, GEMM_SMEM);
    cudaFuncSetAttribute(k_out,  cudaFuncAttributeMaxDynamicSharedMemorySize, GEMM_SMEM);

    __half *xh, *wh, *pwh;
    cudaGetSymbolAddress((void**)&xh,  g_xh);
    cudaGetSymbolAddress((void**)&wh,  g_wh);
    cudaGetSymbolAddress((void**)&pwh, g_pwh);

    k_rowptr<<<(N + 1 + 255) / 256, 256>>>(rows, E, N);

    const int nx4 = (N * 128) / 4;
    k_cvt_x<<<(nx4 + 255) / 256, 256>>>(x, xh, nx4);
    k_cvt_t<<<(16384 + 255) / 256, 256>>>(W,  wh,             128, 128);
    k_cvt_t<<<(16384 + 255) / 256, 256>>>(W2, wh + 16384,     128, 128);
    k_cvt_t<<<(16384 + 255) / 256, 256>>>(W3, wh + 32768,     128, 128);
    k_cvt_t<<<(196608 + 255) / 256, 256>>>(pw, pwh,           1536, 128);

    dim3 gproj((N + 127) / 128, 3);
    k_proj<<<gproj, 256, GEMM_SMEM>>>(N);
    k_agg<<<(N + 7) / 8, 256>>>(cols, vA, vC, N);
    k_out<<<(N + 127) / 128, 256, GEMM_SMEM>>>(pb, out, N);
}

// round 10
// speedup vs baseline: 1.8382x; 1.1322x over previous
#include <cuda_runtime.h>
#include <cuda_fp16.h>
#include <math_constants.h>
#include <cstdint>

#define NNODES 100000
#define NEDGES 1600000

// ---------------- scratch (static __device__ — no allocs allowed) ----------------
__device__ __half g_mh[(size_t)NNODES * 384];     // projected messages, fp16 [N][3*128]
__device__ __half g_fh[(size_t)NNODES * 1536];    // PNA features, fp16 [N][1536]
__device__ __half g_xh[(size_t)NNODES * 128];     // x, fp16
__device__ __half g_wh[3 * 128 * 128];            // W|W2|W3 TRANSPOSED [n][k], fp16
__device__ __half g_pwh[128 * 1536];              // pna_w TRANSPOSED [n=128][k=1536], fp16
__device__ int    g_rowptr[NNODES + 1];

// ---------------- cp.async helpers ----------------
__device__ __forceinline__ void cpasync16(unsigned int dst, const void* src) {
    asm volatile("cp.async.cg.shared.global [%0], [%1], 16;\n" :: "r"(dst), "l"(src));
}
__device__ __forceinline__ void cp_commit() {
    asm volatile("cp.async.commit_group;\n" ::);
}
__device__ __forceinline__ void cp_wait1() {
    asm volatile("cp.async.wait_group 1;\n" ::);
}

// ---------------- fp16 MMA m16n8k16 + ldmatrix ----------------
__device__ __forceinline__ void mma_f16(float* d, const unsigned* a, const unsigned* b) {
    asm volatile(
        "mma.sync.aligned.m16n8k16.row.col.f32.f16.f16.f32 "
        "{%0,%1,%2,%3},{%4,%5,%6,%7},{%8,%9},{%0,%1,%2,%3};\n"
        : "+f"(d[0]), "+f"(d[1]), "+f"(d[2]), "+f"(d[3])
        : "r"(a[0]), "r"(a[1]), "r"(a[2]), "r"(a[3]), "r"(b[0]), "r"(b[1]));
}
__device__ __forceinline__ void ldmx4(unsigned& r0, unsigned& r1, unsigned& r2,
                                      unsigned& r3, unsigned addr) {
    asm volatile("ldmatrix.sync.aligned.m8n8.x4.shared.b16 {%0,%1,%2,%3}, [%4];"
                 : "=r"(r0), "=r"(r1), "=r"(r2), "=r"(r3) : "r"(addr));
}

// ---------------- conversion kernels ----------------
__global__ void k_cvt_x(const float* __restrict__ src, __half* __restrict__ dst, int n4) {
    int i = blockIdx.x * blockDim.x + threadIdx.x;
    if (i < n4) {
        float4 v = *(const float4*)&src[i * 4];
        __half2 h0 = __floats2half2_rn(v.x, v.y);
        __half2 h1 = __floats2half2_rn(v.z, v.w);
        uint2 o;
        o.x = *(unsigned*)&h0;
        o.y = *(unsigned*)&h1;
        *(uint2*)&dst[i * 4] = o;
    }
}

// transpose + convert: src [K][Ncols] fp32 -> dst [Ncols][K] fp16
__global__ void k_cvt_t(const float* __restrict__ src, __half* __restrict__ dst,
                        int K, int Ncols) {
    int i = blockIdx.x * blockDim.x + threadIdx.x;
    if (i < K * Ncols) {
        int k = i / Ncols, n = i % Ncols;
        dst[(size_t)n * K + k] = __float2half_rn(src[i]);
    }
}

// ---------------- row pointers from sorted rows ----------------
__global__ void k_rowptr(const int* __restrict__ rows, int E, int N) {
    int i = blockIdx.x * blockDim.x + threadIdx.x;
    if (i > N) return;
    int lo = 0, hi = E;
    while (lo < hi) {
        int mid = (lo + hi) >> 1;
        if (__ldg(rows + mid) < i) lo = mid + 1; else hi = mid;
    }
    g_rowptr[i] = lo;
}

// =====================================================================
// fp16 MMA GEMM core: 128x128 block tile, 8 warps (2x4), 64x32 warp
// tiles of m16n8k16, 3-stage cp.async ring, ldmatrix fragment loads.
// A [N,LDA] row-major fp16.  B TRANSPOSED [128,LDB] row-major (n,k).
// =====================================================================
#define APADH 24                        // halves per smem row (16 data + 8 pad = 48B)
#define STH   (128 * APADH)             // halves per stage (A or B)
#define GEMM_SMEM (6 * STH * 2)         // 3 stages A + 3 stages B, bytes (36 KB)

template <int NK, int LDA, int LDB>
__device__ __forceinline__ void gemm_fp16_core(
    const __half* __restrict__ Ag, const __half* __restrict__ Bg,
    float acc[4][4][4], int bm, int N, __half* sm) {
    __half* Asb = sm;                // [3][128][APADH]
    __half* Bsb = sm + 3 * STH;      // [3][128][APADH]

    const int tid = threadIdx.x;
    const int lane = tid & 31;
    const int wid = tid >> 5;
    const int wm = wid >> 2, wn = wid & 3;

    // staging: thread -> (row, 16B-half-chunk)
    const int srow = tid >> 1;             // 0..127
    const int shalf = (tid & 1) * 8;       // 0 or 8 halves

    int gr = bm + srow; if (gr >= N) gr = N - 1;
    const __half* sA = Ag + (size_t)gr * LDA + shalf;
    const __half* sB = Bg + (size_t)srow * LDB + shalf;

    const unsigned dA = (unsigned)__cvta_generic_to_shared(&Asb[srow * APADH + shalf]);
    const unsigned dB = (unsigned)__cvta_generic_to_shared(&Bsb[srow * APADH + shalf]);
    const unsigned Abase = (unsigned)__cvta_generic_to_shared(Asb);
    const unsigned Bbase = (unsigned)__cvta_generic_to_shared(Bsb);

    // ldmatrix per-lane byte offsets within a stage
    // A tile (mt): M0=(r0-7,k0) M1=(r8-15,k0) M2=(r0-7,k8) M3=(r8-15,k8)
    const int arow = ((lane >> 3) & 1) * 8 + (lane & 7);
    const int akof = (lane >> 4) * 8;
    unsigned aoff[4];
#pragma unroll
    for (int mt = 0; mt < 4; mt++)
        aoff[mt] = (unsigned)(((wm * 64 + mt * 16 + arow) * APADH + akof) * 2);
    // B pair (p -> nt=2p,2p+1): M0=(n0-7,k0) M1=(n0-7,k8) M2=(n8-15,k0) M3=(n8-15,k8)
    const int brow = (lane & 7) + ((lane >> 4) & 1) * 8;
    const int bkof = ((lane >> 3) & 1) * 8;
    unsigned boff[2];
#pragma unroll
    for (int p = 0; p < 2; p++)
        boff[p] = (unsigned)(((wn * 32 + p * 16 + brow) * APADH + bkof) * 2);

#pragma unroll
    for (int p = 0; p < 2; p++) {   // preload stages 0,1
        cpasync16(dA + p * STH * 2, sA + p * 16);
        cpasync16(dB + p * STH * 2, sB + p * 16);
        cp_commit();
    }

    for (int i = 0; i < NK; i++) {
        cp_wait1();
        __syncthreads();
        const int nc = i + 2;
        if (nc < NK) {
            const int sl = nc - (nc / 3) * 3;
            cpasync16(dA + sl * STH * 2, sA + nc * 16);
            cpasync16(dB + sl * STH * 2, sB + nc * 16);
        }
        cp_commit();

        const int buf = i - (i / 3) * 3;
        const unsigned sa = Abase + buf * STH * 2;
        const unsigned sb = Bbase + buf * STH * 2;

        unsigned afr[4][4], bfr[4][2];
#pragma unroll
        for (int mt = 0; mt < 4; mt++)
            ldmx4(afr[mt][0], afr[mt][1], afr[mt][2], afr[mt][3], sa + aoff[mt]);
#pragma unroll
        for (int p = 0; p < 2; p++)
            ldmx4(bfr[2 * p][0], bfr[2 * p][1], bfr[2 * p + 1][0], bfr[2 * p + 1][1],
                  sb + boff[p]);
#pragma unroll
        for (int mt = 0; mt < 4; mt++)
#pragma unroll
            for (int nt = 0; nt < 4; nt++)
                mma_f16(acc[mt][nt], afr[mt], bfr[nt]);
    }
}

// ---------------- projection GEMM (fp16 MMA): g_mh[:,slab*128+..] = xh @ W[slab] ----------------
__global__ __launch_bounds__(256, 2) void k_proj(int N) {
    extern __shared__ __align__(16) __half smh[];
    const int bm = blockIdx.x * 128;
    const int slab = blockIdx.y;
    float acc[4][4][4] = {};
    gemm_fp16_core<8, 128, 128>(g_xh, g_wh + slab * 128 * 128, acc, bm, N, smh);

    const int lane = threadIdx.x & 31;
    const int wid = threadIdx.x >> 5;
    const int wm = wid >> 2, wn = wid & 3;
    const int tq = lane >> 2, tr = lane & 3;
#pragma unroll
    for (int nt = 0; nt < 4; nt++) {
        const int c0 = slab * 128 + wn * 32 + nt * 8 + 2 * tr;
#pragma unroll
        for (int mt = 0; mt < 4; mt++) {
            const int r0 = bm + wm * 64 + mt * 16 + tq;
            if (r0 < N) {
                __half2 h = __floats2half2_rn(acc[mt][nt][0], acc[mt][nt][1]);
                *(__half2*)&g_mh[(size_t)r0 * 384 + c0] = h;
            }
            const int r1 = r0 + 8;
            if (r1 < N) {
                __half2 h = __floats2half2_rn(acc[mt][nt][2], acc[mt][nt][3]);
                *(__half2*)&g_mh[(size_t)r1 * 384 + c0] = h;
            }
        }
    }
}

// ---------------- aggregation: warp-per-(node,channel) segment stats ----------------
__device__ __forceinline__ float4 h4tof4(uint2 u) {
    __half2 a = *(__half2*)&u.x;
    __half2 b = *(__half2*)&u.y;
    float2 fa = __half22float2(a), fb = __half22float2(b);
    return make_float4(fa.x, fa.y, fb.x, fb.y);
}

__device__ __forceinline__ void agg_upd(float4 v, float s, float4& su, float4& sq,
                                        float4& mx, float4& mn) {
    float gx = v.x * s, gy = v.y * s, gz = v.z * s, gw = v.w * s;
    su.x += gx; su.y += gy; su.z += gz; su.w += gw;
    sq.x += gx * gx; sq.y += gy * gy; sq.z += gz * gz; sq.w += gw * gw;
    mx.x = fmaxf(mx.x, gx); mx.y = fmaxf(mx.y, gy); mx.z = fmaxf(mx.z, gz); mx.w = fmaxf(mx.w, gw);
    mn.x = fminf(mn.x, gx); mn.y = fminf(mn.y, gy); mn.z = fminf(mn.z, gz); mn.w = fminf(mn.w, gw);
}

__device__ __forceinline__ void sth4(__half* p, float4 v) {
    __half2 h0 = __floats2half2_rn(v.x, v.y);
    __half2 h1 = __floats2half2_rn(v.z, v.w);
    uint2 o; o.x = *(unsigned*)&h0; o.y = *(unsigned*)&h1;
    *(uint2*)p = o;
}

__global__ __launch_bounds__(256) void k_agg(const int* __restrict__ cols,
                                             const float* __restrict__ vA,
                                             const float* __restrict__ vC, int N) {
    int gw = (blockIdx.x * blockDim.x + threadIdx.x) >> 5;  // global warp
    int lane = threadIdx.x & 31;
    if (gw >= 3 * N) return;
    const int node = gw / 3;
    const int ch = gw - 3 * node;         // 0: vA, 1: vC, 2: vA*vC
    const int r0 = g_rowptr[node], r1 = g_rowptr[node + 1];

    const float NEG = -CUDART_INF_F, POS = CUDART_INF_F;
    float4 su = {0, 0, 0, 0}, sq = {0, 0, 0, 0};
    float4 mx = {NEG, NEG, NEG, NEG}, mn = {POS, POS, POS, POS};

    const __half* mbase = g_mh + (size_t)ch * 128 + lane * 4;

    int e = r0;
    for (; e + 2 <= r1; e += 2) {  // 2-edge unroll for load MLP
        int ca = __ldg(cols + e), cb = __ldg(cols + e + 1);
        float aa = __ldg(vA + e), ab = __ldg(vA + e + 1);
        float ba = __ldg(vC + e), bb = __ldg(vC + e + 1);
        float s0 = (ch == 0) ? aa : (ch == 1) ? ba : aa * ba;
        float s1 = (ch == 0) ? ab : (ch == 1) ? bb : ab * bb;
        uint2 u = __ldg((const uint2*)(mbase + (size_t)ca * 384));
        uint2 w = __ldg((const uint2*)(mbase + (size_t)cb * 384));
        agg_upd(h4tof4(u), s0, su, sq, mx, mn);
        agg_upd(h4tof4(w), s1, su, sq, mx, mn);
    }
    for (; e < r1; e++) {
        int c = __ldg(cols + e);
        float a = __ldg(vA + e);
        float b = __ldg(vC + e);
        float s = (ch == 0) ? a : (ch == 1) ? b : a * b;
        uint2 u = __ldg((const uint2*)(mbase + (size_t)c * 384));
        agg_upd(h4tof4(u), s, su, sq, mx, mn);
    }

    const int deg = r1 - r0;
    const float inv = 1.f / fmaxf((float)deg, 1.f);
    float4 mean, var, sd;
    mean.x = su.x * inv; mean.y = su.y * inv; mean.z = su.z * inv; mean.w = su.w * inv;
    var.x = fmaxf(sq.x * inv - mean.x * mean.x, 0.f);
    var.y = fmaxf(sq.y * inv - mean.y * mean.y, 0.f);
    var.z = fmaxf(sq.z * inv - mean.z * mean.z, 0.f);
    var.w = fmaxf(sq.w * inv - mean.w * mean.w, 0.f);
    sd.x = sqrtf(var.x + 1e-5f); sd.y = sqrtf(var.y + 1e-5f);
    sd.z = sqrtf(var.z + 1e-5f); sd.w = sqrtf(var.w + 1e-5f);
    if (deg == 0) {
        mx = make_float4(0.f, 0.f, 0.f, 0.f);
        mn = make_float4(0.f, 0.f, 0.f, 0.f);
    }
    __half* fb = g_fh + (size_t)node * 1536 + ch * 512 + lane * 4;
    sth4(fb,       mean);
    sth4(fb + 128, mx);
    sth4(fb + 256, mn);
    sth4(fb + 384, sd);
}

// ---------------- output GEMM (fp16 MMA): out = feats @ pw + sum(pna_b) ----------------
__global__ __launch_bounds__(256, 2) void k_out(const float* __restrict__ pb,
                                                float* __restrict__ out, int N) {
    extern __shared__ __align__(16) __half smh[];
    const int bm = blockIdx.x * 128;
    float acc[4][4][4] = {};
    gemm_fp16_core<96, 1536, 1536>(g_fh, g_pwh, acc, bm, N, smh);

    const int lane = threadIdx.x & 31;
    const int wid = threadIdx.x >> 5;
    const int wm = wid >> 2, wn = wid & 3;
    const int tq = lane >> 2, tr = lane & 3;
#pragma unroll
    for (int nt = 0; nt < 4; nt++) {
        const int c0 = wn * 32 + nt * 8 + 2 * tr;
        const float b0 = __ldg(pb + c0) + __ldg(pb + 128 + c0) + __ldg(pb + 256 + c0);
        const float b1 = __ldg(pb + c0 + 1) + __ldg(pb + 128 + c0 + 1) + __ldg(pb + 256 + c0 + 1);
#pragma unroll
        for (int mt = 0; mt < 4; mt++) {
            const int r0 = bm + wm * 64 + mt * 16 + tq;
            if (r0 < N) {
                float2 v = make_float2(acc[mt][nt][0] + b0, acc[mt][nt][1] + b1);
                *(float2*)&out[(size_t)r0 * 128 + c0] = v;
            }
            const int r1 = r0 + 8;
            if (r1 < N) {
                float2 v = make_float2(acc[mt][nt][2] + b0, acc[mt][nt][3] + b1);
                *(float2*)&out[(size_t)r1 * 128 + c0] = v;
            }
        }
    }
}

// ---------------- launch ----------------
extern "C" void kernel_launch(void* const* d_in, const int* in_sizes, int n_in,
                              void* d_out, int out_size) {
    const float* x    = (const float*)d_in[0];
    const int*   rows = (const int*)d_in[1];
    const int*   cols = (const int*)d_in[2];
    const float* vA   = (const float*)d_in[3];
    const float* vC   = (const float*)d_in[4];
    const float* W    = (const float*)d_in[5];
    const float* W2   = (const float*)d_in[6];
    const float* W3   = (const float*)d_in[7];
    const float* pw   = (const float*)d_in[8];  // [3,512,128] == flat [1536,128]
    const float* pb   = (const float*)d_in[9];  // [3,128]
    float* out = (float*)d_out;

    const int N = in_sizes[0] / 128;
    const int E = in_sizes[1];

    // idempotent, not stream-ordered; safe under graph capture
    cudaFuncSetAttribute(k_proj, cudaFuncAttributeMaxDynamicSharedMemorySize, GEMM_SMEM);
    cudaFuncSetAttribute(k_out,  cudaFuncAttributeMaxDynamicSharedMemorySize, GEMM_SMEM);

    __half *xh, *wh, *pwh;
    cudaGetSymbolAddress((void**)&xh,  g_xh);
    cudaGetSymbolAddress((void**)&wh,  g_wh);
    cudaGetSymbolAddress((void**)&pwh, g_pwh);

    k_rowptr<<<(N + 1 + 255) / 256, 256>>>(rows, E, N);

    const int nx4 = (N * 128) / 4;
    k_cvt_x<<<(nx4 + 255) / 256, 256>>>(x, xh, nx4);
    k_cvt_t<<<(16384 + 255) / 256, 256>>>(W,  wh,             128, 128);
    k_cvt_t<<<(16384 + 255) / 256, 256>>>(W2, wh + 16384,     128, 128);
    k_cvt_t<<<(16384 + 255) / 256, 256>>>(W3, wh + 32768,     128, 128);
    k_cvt_t<<<(196608 + 255) / 256, 256>>>(pw, pwh,           1536, 128);

    dim3 gproj((N + 127) / 128, 3);
    k_proj<<<gproj, 256, GEMM_SMEM>>>(N);
    const int aggwarps = 3 * N;
    k_agg<<<(aggwarps + 7) / 8, 256>>>(cols, vA, vC, N);
    k_out<<<(N + 127) / 128, 256, GEMM_SMEM>>>(pb, out, N);
}

// round 12
// speedup vs baseline: 1.8645x; 1.0143x over previous
#include <cuda_runtime.h>
#include <cuda_fp16.h>
#include <math_constants.h>
#include <cstdint>

#define NNODES 100000
#define NEDGES 1600000

// ---------------- scratch (static __device__ — no allocs allowed) ----------------
__device__ __half g_mh[(size_t)NNODES * 384];     // projected messages, fp16 [N][3*128]
__device__ __half g_fh[(size_t)NNODES * 1536];    // PNA features, fp16 [N][1536]
__device__ __half g_xh[(size_t)NNODES * 128];     // x, fp16
__device__ __half g_wh[3 * 128 * 128];            // W|W2|W3 TRANSPOSED [n][k], fp16
__device__ __half g_pwh[128 * 1536];              // pna_w TRANSPOSED [n=128][k=1536], fp16
__device__ int    g_rowptr[NNODES + 1];

// ---------------- cp.async helpers ----------------
__device__ __forceinline__ void cpasync16(unsigned int dst, const void* src) {
    asm volatile("cp.async.cg.shared.global [%0], [%1], 16;\n" :: "r"(dst), "l"(src));
}
__device__ __forceinline__ void cp_commit() {
    asm volatile("cp.async.commit_group;\n" ::);
}
__device__ __forceinline__ void cp_wait1() {
    asm volatile("cp.async.wait_group 1;\n" ::);
}

// ---------------- fp16 MMA m16n8k16 + ldmatrix ----------------
__device__ __forceinline__ void mma_f16(float* d, const unsigned* a, const unsigned* b) {
    asm volatile(
        "mma.sync.aligned.m16n8k16.row.col.f32.f16.f16.f32 "
        "{%0,%1,%2,%3},{%4,%5,%6,%7},{%8,%9},{%0,%1,%2,%3};\n"
        : "+f"(d[0]), "+f"(d[1]), "+f"(d[2]), "+f"(d[3])
        : "r"(a[0]), "r"(a[1]), "r"(a[2]), "r"(a[3]), "r"(b[0]), "r"(b[1]));
}
__device__ __forceinline__ void ldmx4(unsigned& r0, unsigned& r1, unsigned& r2,
                                      unsigned& r3, unsigned addr) {
    asm volatile("ldmatrix.sync.aligned.m8n8.x4.shared.b16 {%0,%1,%2,%3}, [%4];"
                 : "=r"(r0), "=r"(r1), "=r"(r2), "=r"(r3) : "r"(addr));
}

// ---------------- conversion kernels ----------------
__global__ void k_cvt_x(const float* __restrict__ src, __half* __restrict__ dst, int n4) {
    int i = blockIdx.x * blockDim.x + threadIdx.x;
    if (i < n4) {
        float4 v = *(const float4*)&src[i * 4];
        __half2 h0 = __floats2half2_rn(v.x, v.y);
        __half2 h1 = __floats2half2_rn(v.z, v.w);
        uint2 o;
        o.x = *(unsigned*)&h0;
        o.y = *(unsigned*)&h1;
        *(uint2*)&dst[i * 4] = o;
    }
}

// transpose + convert the 3 projection weights: src [128][128] -> dst [n][k]
__global__ void k_cvt_w3(const float* __restrict__ W, const float* __restrict__ W2,
                         const float* __restrict__ W3, __half* __restrict__ dst) {
    const int slab = blockIdx.y;
    const float* src = (slab == 0) ? W : (slab == 1) ? W2 : W3;
    int i = blockIdx.x * blockDim.x + threadIdx.x;
    if (i < 128 * 128) {
        int k = i >> 7, n = i & 127;
        dst[slab * 16384 + n * 128 + k] = __float2half_rn(src[i]);
    }
}

// transpose + convert: src [K][Ncols] fp32 -> dst [Ncols][K] fp16
__global__ void k_cvt_t(const float* __restrict__ src, __half* __restrict__ dst,
                        int K, int Ncols) {
    int i = blockIdx.x * blockDim.x + threadIdx.x;
    if (i < K * Ncols) {
        int k = i / Ncols, n = i % Ncols;
        dst[(size_t)n * K + k] = __float2half_rn(src[i]);
    }
}

// ---------------- row pointers from sorted rows ----------------
__global__ void k_rowptr(const int* __restrict__ rows, int E, int N) {
    int i = blockIdx.x * blockDim.x + threadIdx.x;
    if (i > N) return;
    int lo = 0, hi = E;
    while (lo < hi) {
        int mid = (lo + hi) >> 1;
        if (__ldg(rows + mid) < i) lo = mid + 1; else hi = mid;
    }
    g_rowptr[i] = lo;
}

// =====================================================================
// fp16 MMA GEMM core v2: 128x128 block tile, 8 warps (2x4), 64x32 warp
// tiles of m16n8k16, 3-stage cp.async ring, K-chunk 32, ldmatrix loads.
// A [N,LDA] row-major fp16.  B TRANSPOSED [128,LDB] row-major (n,k).
// =====================================================================
#define RPADH 40                        // halves per smem row (32 data + 8 pad = 80B)
#define STH   (128 * RPADH)             // halves per stage (A or B)
#define GEMM_SMEM (6 * STH * 2)         // 3 stages A + 3 stages B = 60 KB

template <int NK2, int LDA, int LDB>
__device__ __forceinline__ void gemm_fp16_core(
    const __half* __restrict__ Ag, const __half* __restrict__ Bg,
    float acc[4][4][4], int bm, int N, __half* sm) {
    __half* Asb = sm;                // [3][128][RPADH]
    __half* Bsb = sm + 3 * STH;      // [3][128][RPADH]

    const int tid = threadIdx.x;
    const int lane = tid & 31;
    const int wid = tid >> 5;
    const int wm = wid >> 2, wn = wid & 3;

    // staging: thread -> (row, 32B half-pair of the 64B row)
    const int srow = tid >> 1;              // 0..127
    const int shalf = (tid & 1) * 16;       // 0 or 16 halves

    int gr = bm + srow; if (gr >= N) gr = N - 1;
    const __half* sA = Ag + (size_t)gr * LDA + shalf;
    const __half* sB = Bg + (size_t)srow * LDB + shalf;

    const unsigned dA = (unsigned)__cvta_generic_to_shared(&Asb[srow * RPADH + shalf]);
    const unsigned dB = (unsigned)__cvta_generic_to_shared(&Bsb[srow * RPADH + shalf]);
    const unsigned Abase = (unsigned)__cvta_generic_to_shared(Asb);
    const unsigned Bbase = (unsigned)__cvta_generic_to_shared(Bsb);

    // ldmatrix per-lane byte offsets within a stage (k16 step s adds s*32 bytes)
    const int arow = ((lane >> 3) & 1) * 8 + (lane & 7);
    const int akof = (lane >> 4) * 8;
    unsigned aoff[4];
#pragma unroll
    for (int mt = 0; mt < 4; mt++)
        aoff[mt] = (unsigned)(((wm * 64 + mt * 16 + arow) * RPADH + akof) * 2);
    const int brow = (lane & 7) + ((lane >> 4) & 1) * 8;
    const int bkof = ((lane >> 3) & 1) * 8;
    unsigned boff[2];
#pragma unroll
    for (int p = 0; p < 2; p++)
        boff[p] = (unsigned)(((wn * 32 + p * 16 + brow) * RPADH + bkof) * 2);

#pragma unroll
    for (int p = 0; p < 2; p++) {   // preload stages 0,1 (each = 32 k-halves)
        cpasync16(dA + p * STH * 2, sA + p * 32);
        cpasync16(dA + p * STH * 2 + 16, sA + p * 32 + 8);
        cpasync16(dB + p * STH * 2, sB + p * 32);
        cpasync16(dB + p * STH * 2 + 16, sB + p * 32 + 8);
        cp_commit();
    }

    for (int i = 0; i < NK2; i++) {
        cp_wait1();
        __syncthreads();
        const int nc = i + 2;
        if (nc < NK2) {
            const int sl = nc - (nc / 3) * 3;
            cpasync16(dA + sl * STH * 2, sA + nc * 32);
            cpasync16(dA + sl * STH * 2 + 16, sA + nc * 32 + 8);
            cpasync16(dB + sl * STH * 2, sB + nc * 32);
            cpasync16(dB + sl * STH * 2 + 16, sB + nc * 32 + 8);
        }
        cp_commit();

        const int buf = i - (i / 3) * 3;
        const unsigned sa = Abase + buf * STH * 2;
        const unsigned sb = Bbase + buf * STH * 2;

#pragma unroll
        for (int s = 0; s < 2; s++) {   // two k16 steps per stage
            unsigned afr[4][4], bfr[4][2];
#pragma unroll
            for (int mt = 0; mt < 4; mt++)
                ldmx4(afr[mt][0], afr[mt][1], afr[mt][2], afr[mt][3],
                      sa + aoff[mt] + s * 32);
#pragma unroll
            for (int p = 0; p < 2; p++)
                ldmx4(bfr[2 * p][0], bfr[2 * p][1], bfr[2 * p + 1][0], bfr[2 * p + 1][1],
                      sb + boff[p] + s * 32);
#pragma unroll
            for (int mt = 0; mt < 4; mt++)
#pragma unroll
                for (int nt = 0; nt < 4; nt++)
                    mma_f16(acc[mt][nt], afr[mt], bfr[nt]);
        }
    }
}

// ---------------- projection GEMM (fp16 MMA): g_mh[:,slab*128+..] = xh @ W[slab] ----------------
__global__ __launch_bounds__(256, 2) void k_proj(int N) {
    extern __shared__ __align__(16) __half smh[];
    const int bm = blockIdx.x * 128;
    const int slab = blockIdx.y;
    float acc[4][4][4] = {};
    gemm_fp16_core<4, 128, 128>(g_xh, g_wh + slab * 128 * 128, acc, bm, N, smh);

    const int lane = threadIdx.x & 31;
    const int wid = threadIdx.x >> 5;
    const int wm = wid >> 2, wn = wid & 3;
    const int tq = lane >> 2, tr = lane & 3;
#pragma unroll
    for (int nt = 0; nt < 4; nt++) {
        const int c0 = slab * 128 + wn * 32 + nt * 8 + 2 * tr;
#pragma unroll
        for (int mt = 0; mt < 4; mt++) {
            const int r0 = bm + wm * 64 + mt * 16 + tq;
            if (r0 < N) {
                __half2 h = __floats2half2_rn(acc[mt][nt][0], acc[mt][nt][1]);
                *(__half2*)&g_mh[(size_t)r0 * 384 + c0] = h;
            }
            const int r1 = r0 + 8;
            if (r1 < N) {
                __half2 h = __floats2half2_rn(acc[mt][nt][2], acc[mt][nt][3]);
                *(__half2*)&g_mh[(size_t)r1 * 384 + c0] = h;
            }
        }
    }
}

// ---------------- aggregation: warp-per-(node,channel) segment stats ----------------
__device__ __forceinline__ float4 h4tof4(uint2 u) {
    __half2 a = *(__half2*)&u.x;
    __half2 b = *(__half2*)&u.y;
    float2 fa = __half22float2(a), fb = __half22float2(b);
    return make_float4(fa.x, fa.y, fb.x, fb.y);
}

__device__ __forceinline__ void agg_upd(float4 v, float s, float4& su, float4& sq,
                                        float4& mx, float4& mn) {
    float gx = v.x * s, gy = v.y * s, gz = v.z * s, gw = v.w * s;
    su.x += gx; su.y += gy; su.z += gz; su.w += gw;
    sq.x += gx * gx; sq.y += gy * gy; sq.z += gz * gz; sq.w += gw * gw;
    mx.x = fmaxf(mx.x, gx); mx.y = fmaxf(mx.y, gy); mx.z = fmaxf(mx.z, gz); mx.w = fmaxf(mx.w, gw);
    mn.x = fminf(mn.x, gx); mn.y = fminf(mn.y, gy); mn.z = fminf(mn.z, gz); mn.w = fminf(mn.w, gw);
}

__device__ __forceinline__ void sth4(__half* p, float4 v) {
    __half2 h0 = __floats2half2_rn(v.x, v.y);
    __half2 h1 = __floats2half2_rn(v.z, v.w);
    uint2 o; o.x = *(unsigned*)&h0; o.y = *(unsigned*)&h1;
    *(uint2*)p = o;
}

__global__ __launch_bounds__(256) void k_agg(const int* __restrict__ cols,
                                             const float* __restrict__ vA,
                                             const float* __restrict__ vC, int N) {
    int gw = (blockIdx.x * blockDim.x + threadIdx.x) >> 5;  // global warp
    int lane = threadIdx.x & 31;
    if (gw >= 3 * N) return;
    const int node = gw / 3;
    const int ch = gw - 3 * node;         // 0: vA, 1: vC, 2: vA*vC
    const int r0 = g_rowptr[node], r1 = g_rowptr[node + 1];

    const float NEG = -CUDART_INF_F, POS = CUDART_INF_F;
    float4 su = {0, 0, 0, 0}, sq = {0, 0, 0, 0};
    float4 mx = {NEG, NEG, NEG, NEG}, mn = {POS, POS, POS, POS};

    const __half* mbase = g_mh + (size_t)ch * 128 + lane * 4;

    int e = r0;
    for (; e + 4 <= r1; e += 4) {  // 4-edge unroll for load MLP
        int c0 = __ldg(cols + e),     c1 = __ldg(cols + e + 1);
        int c2 = __ldg(cols + e + 2), c3 = __ldg(cols + e + 3);
        float a0 = __ldg(vA + e),     a1 = __ldg(vA + e + 1);
        float a2 = __ldg(vA + e + 2), a3 = __ldg(vA + e + 3);
        float b0 = __ldg(vC + e),     b1 = __ldg(vC + e + 1);
        float b2 = __ldg(vC + e + 2), b3 = __ldg(vC + e + 3);
        float s0 = (ch == 0) ? a0 : (ch == 1) ? b0 : a0 * b0;
        float s1 = (ch == 0) ? a1 : (ch == 1) ? b1 : a1 * b1;
        float s2 = (ch == 0) ? a2 : (ch == 1) ? b2 : a2 * b2;
        float s3 = (ch == 0) ? a3 : (ch == 1) ? b3 : a3 * b3;
        uint2 u0 = __ldg((const uint2*)(mbase + (size_t)c0 * 384));
        uint2 u1 = __ldg((const uint2*)(mbase + (size_t)c1 * 384));
        uint2 u2 = __ldg((const uint2*)(mbase + (size_t)c2 * 384));
        uint2 u3 = __ldg((const uint2*)(mbase + (size_t)c3 * 384));
        agg_upd(h4tof4(u0), s0, su, sq, mx, mn);
        agg_upd(h4tof4(u1), s1, su, sq, mx, mn);
        agg_upd(h4tof4(u2), s2, su, sq, mx, mn);
        agg_upd(h4tof4(u3), s3, su, sq, mx, mn);
    }
    for (; e < r1; e++) {
        int c = __ldg(cols + e);
        float a = __ldg(vA + e);
        float b = __ldg(vC + e);
        float s = (ch == 0) ? a : (ch == 1) ? b : a * b;
        uint2 u = __ldg((const uint2*)(mbase + (size_t)c * 384));
        agg_upd(h4tof4(u), s, su, sq, mx, mn);
    }

    const int deg = r1 - r0;
    const float inv = 1.f / fmaxf((float)deg, 1.f);
    float4 mean, var, sd;
    mean.x = su.x * inv; mean.y = su.y * inv; mean.z = su.z * inv; mean.w = su.w * inv;
    var.x = fmaxf(sq.x * inv - mean.x * mean.x, 0.f);
    var.y = fmaxf(sq.y * inv - mean.y * mean.y, 0.f);
    var.z = fmaxf(sq.z * inv - mean.z * mean.z, 0.f);
    var.w = fmaxf(sq.w * inv - mean.w * mean.w, 0.f);
    sd.x = sqrtf(var.x + 1e-5f); sd.y = sqrtf(var.y + 1e-5f);
    sd.z = sqrtf(var.z + 1e-5f); sd.w = sqrtf(var.w + 1e-5f);
    if (deg == 0) {
        mx = make_float4(0.f, 0.f, 0.f, 0.f);
        mn = make_float4(0.f, 0.f, 0.f, 0.f);
    }
    __half* fb = g_fh + (size_t)node * 1536 + ch * 512 + lane * 4;
    sth4(fb,       mean);
    sth4(fb + 128, mx);
    sth4(fb + 256, mn);
    sth4(fb + 384, sd);
}

// ---------------- output GEMM (fp16 MMA): out = feats @ pw + sum(pna_b) ----------------
__global__ __launch_bounds__(256, 2) void k_out(const float* __restrict__ pb,
                                                float* __restrict__ out, int N) {
    extern __shared__ __align__(16) __half smh[];
    const int bm = blockIdx.x * 128;
    float acc[4][4][4] = {};
    gemm_fp16_core<48, 1536, 1536>(g_fh, g_pwh, acc, bm, N, smh);

    const int lane = threadIdx.x & 31;
    const int wid = threadIdx.x >> 5;
    const int wm = wid >> 2, wn = wid & 3;
    const int tq = lane >> 2, tr = lane & 3;
#pragma unroll
    for (int nt = 0; nt < 4; nt++) {
        const int c0 = wn * 32 + nt * 8 + 2 * tr;
        const float b0 = __ldg(pb + c0) + __ldg(pb + 128 + c0) + __ldg(pb + 256 + c0);
        const float b1 = __ldg(pb + c0 + 1) + __ldg(pb + 128 + c0 + 1) + __ldg(pb + 256 + c0 + 1);
#pragma unroll
        for (int mt = 0; mt < 4; mt++) {
            const int r0 = bm + wm * 64 + mt * 16 + tq;
            if (r0 < N) {
                float2 v = make_float2(acc[mt][nt][0] + b0, acc[mt][nt][1] + b1);
                *(float2*)&out[(size_t)r0 * 128 + c0] = v;
            }
            const int r1 = r0 + 8;
            if (r1 < N) {
                float2 v = make_float2(acc[mt][nt][2] + b0, acc[mt][nt][3] + b1);
                *(float2*)&out[(size_t)r1 * 128 + c0] = v;
            }
        }
    }
}

// ---------------- launch ----------------
extern "C" void kernel_launch(void* const* d_in, const int* in_sizes, int n_in,
                              void* d_out, int out_size) {
    const float* x    = (const float*)d_in[0];
    const int*   rows = (const int*)d_in[1];
    const int*   cols = (const int*)d_in[2];
    const float* vA   = (const float*)d_in[3];
    const float* vC   = (const float*)d_in[4];
    const float* W    = (const float*)d_in[5];
    const float* W2   = (const float*)d_in[6];
    const float* W3   = (const float*)d_in[7];
    const float* pw   = (const float*)d_in[8];  // [3,512,128] == flat [1536,128]
    const float* pb   = (const float*)d_in[9];  // [3,128]
    float* out = (float*)d_out;

    const int N = in_sizes[0] / 128;
    const int E = in_sizes[1];

    // idempotent, not stream-ordered; safe under graph capture
    cudaFuncSetAttribute(k_proj, cudaFuncAttributeMaxDynamicSharedMemorySize, GEMM_SMEM);
    cudaFuncSetAttribute(k_out,  cudaFuncAttributeMaxDynamicSharedMemorySize, GEMM_SMEM);

    __half *xh, *wh, *pwh;
    cudaGetSymbolAddress((void**)&xh,  g_xh);
    cudaGetSymbolAddress((void**)&wh,  g_wh);
    cudaGetSymbolAddress((void**)&pwh, g_pwh);

    k_rowptr<<<(N + 1 + 255) / 256, 256>>>(rows, E, N);

    const int nx4 = (N * 128) / 4;
    k_cvt_x<<<(nx4 + 255) / 256, 256>>>(x, xh, nx4);
    dim3 gw3((16384 + 255) / 256, 3);
    k_cvt_w3<<<gw3, 256>>>(W, W2, W3, wh);
    k_cvt_t<<<(196608 + 255) / 256, 256>>>(pw, pwh, 1536, 128);

    dim3 gproj((N + 127) / 128, 3);
    k_proj<<<gproj, 256, GEMM_SMEM>>>(N);
    const int aggwarps = 3 * N;
    k_agg<<<(aggwarps + 7) / 8, 256>>>(cols, vA, vC, N);
    k_out<<<(N + 127) / 128, 256, GEMM_SMEM>>>(pb, out, N);
}

// round 13
// speedup vs baseline: 1.9202x; 1.0299x over previous
#include <cuda_runtime.h>
#include <cuda_fp16.h>
#include <math_constants.h>
#include <cstdint>

#define NNODES 100000
#define NEDGES 1600000

// ---------------- scratch (static __device__ — no allocs allowed) ----------------
__device__ __half g_mh[(size_t)NNODES * 384];     // projected messages, fp16 [N][3*128]
__device__ __half g_fh[(size_t)NNODES * 1536];    // PNA features, fp16 [N][1536]
__device__ __half g_wh[3 * 128 * 128];            // W|W2|W3 TRANSPOSED [n][k], fp16
__device__ __half g_pwh[128 * 1536];              // pna_w TRANSPOSED [n=128][k=1536], fp16
__device__ int    g_rowptr[NNODES + 1];

// ---------------- cp.async helpers ----------------
__device__ __forceinline__ void cpasync16(unsigned int dst, const void* src) {
    asm volatile("cp.async.cg.shared.global [%0], [%1], 16;\n" :: "r"(dst), "l"(src));
}
__device__ __forceinline__ void cp_commit() {
    asm volatile("cp.async.commit_group;\n" ::);
}
__device__ __forceinline__ void cp_wait1() {
    asm volatile("cp.async.wait_group 1;\n" ::);
}

// ---------------- fp16 MMA m16n8k16 + ldmatrix ----------------
__device__ __forceinline__ void mma_f16(float* d, const unsigned* a, const unsigned* b) {
    asm volatile(
        "mma.sync.aligned.m16n8k16.row.col.f32.f16.f16.f32 "
        "{%0,%1,%2,%3},{%4,%5,%6,%7},{%8,%9},{%0,%1,%2,%3};\n"
        : "+f"(d[0]), "+f"(d[1]), "+f"(d[2]), "+f"(d[3])
        : "r"(a[0]), "r"(a[1]), "r"(a[2]), "r"(a[3]), "r"(b[0]), "r"(b[1]));
}
__device__ __forceinline__ void ldmx4(unsigned& r0, unsigned& r1, unsigned& r2,
                                      unsigned& r3, unsigned addr) {
    asm volatile("ldmatrix.sync.aligned.m8n8.x4.shared.b16 {%0,%1,%2,%3}, [%4];"
                 : "=r"(r0), "=r"(r1), "=r"(r2), "=r"(r3) : "r"(addr));
}

// ---------------- conversion kernels ----------------
// transpose + convert the 3 projection weights: src [128][128] -> dst [n][k]
__global__ void k_cvt_w3(const float* __restrict__ W, const float* __restrict__ W2,
                         const float* __restrict__ W3, __half* __restrict__ dst) {
    const int slab = blockIdx.y;
    const float* src = (slab == 0) ? W : (slab == 1) ? W2 : W3;
    int i = blockIdx.x * blockDim.x + threadIdx.x;
    if (i < 128 * 128) {
        int k = i >> 7, n = i & 127;
        dst[slab * 16384 + n * 128 + k] = __float2half_rn(src[i]);
    }
}

// transpose + convert: src [K][Ncols] fp32 -> dst [Ncols][K] fp16
__global__ void k_cvt_t(const float* __restrict__ src, __half* __restrict__ dst,
                        int K, int Ncols) {
    int i = blockIdx.x * blockDim.x + threadIdx.x;
    if (i < K * Ncols) {
        int k = i / Ncols, n = i % Ncols;
        dst[(size_t)n * K + k] = __float2half_rn(src[i]);
    }
}

// ---------------- row pointers from sorted rows ----------------
__global__ void k_rowptr(const int* __restrict__ rows, int E, int N) {
    int i = blockIdx.x * blockDim.x + threadIdx.x;
    if (i > N) return;
    int lo = 0, hi = E;
    while (lo < hi) {
        int mid = (lo + hi) >> 1;
        if (__ldg(rows + mid) < i) lo = mid + 1; else hi = mid;
    }
    g_rowptr[i] = lo;
}

// =====================================================================
// fp16 MMA GEMM core v2 (k_out): 128x128 block tile, 8 warps (2x4),
// 64x32 warp tiles, m16n8k16, 3-stage cp.async ring, K-chunk 32.
// A [N,LDA] row-major fp16.  B TRANSPOSED [128,LDB] row-major (n,k).
// =====================================================================
#define RPADH 40                        // halves per smem row (32 data + 8 pad = 80B)
#define STH   (128 * RPADH)             // halves per stage (A or B)
#define GEMM_SMEM (6 * STH * 2)         // 3 stages A + 3 stages B = 60 KB

template <int NK2, int LDA, int LDB>
__device__ __forceinline__ void gemm_fp16_core(
    const __half* __restrict__ Ag, const __half* __restrict__ Bg,
    float acc[4][4][4], int bm, int N, __half* sm) {
    __half* Asb = sm;                // [3][128][RPADH]
    __half* Bsb = sm + 3 * STH;      // [3][128][RPADH]

    const int tid = threadIdx.x;
    const int lane = tid & 31;
    const int wid = tid >> 5;
    const int wm = wid >> 2, wn = wid & 3;

    const int srow = tid >> 1;              // 0..127
    const int shalf = (tid & 1) * 16;       // 0 or 16 halves

    int gr = bm + srow; if (gr >= N) gr = N - 1;
    const __half* sA = Ag + (size_t)gr * LDA + shalf;
    const __half* sB = Bg + (size_t)srow * LDB + shalf;

    const unsigned dA = (unsigned)__cvta_generic_to_shared(&Asb[srow * RPADH + shalf]);
    const unsigned dB = (unsigned)__cvta_generic_to_shared(&Bsb[srow * RPADH + shalf]);
    const unsigned Abase = (unsigned)__cvta_generic_to_shared(Asb);
    const unsigned Bbase = (unsigned)__cvta_generic_to_shared(Bsb);

    const int arow = ((lane >> 3) & 1) * 8 + (lane & 7);
    const int akof = (lane >> 4) * 8;
    unsigned aoff[4];
#pragma unroll
    for (int mt = 0; mt < 4; mt++)
        aoff[mt] = (unsigned)(((wm * 64 + mt * 16 + arow) * RPADH + akof) * 2);
    const int brow = (lane & 7) + ((lane >> 4) & 1) * 8;
    const int bkof = ((lane >> 3) & 1) * 8;
    unsigned boff[2];
#pragma unroll
    for (int p = 0; p < 2; p++)
        boff[p] = (unsigned)(((wn * 32 + p * 16 + brow) * RPADH + bkof) * 2);

#pragma unroll
    for (int p = 0; p < 2; p++) {
        cpasync16(dA + p * STH * 2, sA + p * 32);
        cpasync16(dA + p * STH * 2 + 16, sA + p * 32 + 8);
        cpasync16(dB + p * STH * 2, sB + p * 32);
        cpasync16(dB + p * STH * 2 + 16, sB + p * 32 + 8);
        cp_commit();
    }

    for (int i = 0; i < NK2; i++) {
        cp_wait1();
        __syncthreads();
        const int nc = i + 2;
        if (nc < NK2) {
            const int sl = nc - (nc / 3) * 3;
            cpasync16(dA + sl * STH * 2, sA + nc * 32);
            cpasync16(dA + sl * STH * 2 + 16, sA + nc * 32 + 8);
            cpasync16(dB + sl * STH * 2, sB + nc * 32);
            cpasync16(dB + sl * STH * 2 + 16, sB + nc * 32 + 8);
        }
        cp_commit();

        const int buf = i - (i / 3) * 3;
        const unsigned sa = Abase + buf * STH * 2;
        const unsigned sb = Bbase + buf * STH * 2;

#pragma unroll
        for (int s = 0; s < 2; s++) {
            unsigned afr[4][4], bfr[4][2];
#pragma unroll
            for (int mt = 0; mt < 4; mt++)
                ldmx4(afr[mt][0], afr[mt][1], afr[mt][2], afr[mt][3],
                      sa + aoff[mt] + s * 32);
#pragma unroll
            for (int p = 0; p < 2; p++)
                ldmx4(bfr[2 * p][0], bfr[2 * p][1], bfr[2 * p + 1][0], bfr[2 * p + 1][1],
                      sb + boff[p] + s * 32);
#pragma unroll
            for (int mt = 0; mt < 4; mt++)
#pragma unroll
                for (int nt = 0; nt < 4; nt++)
                    mma_f16(acc[mt][nt], afr[mt], bfr[nt]);
        }
    }
}

// =====================================================================
// projection GEMM v2: one block = 128 rows x ALL 3 slabs.
// A (128x128 fp16) staged ONCE from fp32 x (fused conversion);
// per-slab B ring (4 chunks of k32). Writes g_mh[:, slab*128..].
// =====================================================================
#define APROW 136                        // halves per A smem row (128 + 8 pad = 272B)
#define PROJ_ASZ (128 * APROW)           // halves
#define PROJ_SMEM ((PROJ_ASZ + 3 * STH) * 2)   // 34816 + 30720 = 65536 B

__global__ __launch_bounds__(256, 2) void k_proj(const float* __restrict__ x, int N) {
    extern __shared__ __align__(16) __half smh[];
    __half* Ah  = smh;                   // [128][APROW]
    __half* Bsb = smh + PROJ_ASZ;        // [3][128][RPADH]

    const int bm = blockIdx.x * 128;
    const int tid = threadIdx.x;
    const int lane = tid & 31;
    const int wid = tid >> 5;
    const int wm = wid >> 2, wn = wid & 3;
    const int tq = lane >> 2, tr = lane & 3;

    // ---- stage A from fp32 x, converting to fp16 (one time) ----
#pragma unroll
    for (int j = 0; j < 16; j++) {
        int i = tid + j * 256;           // 0..4095 over 128 rows x 32 float4
        int row = i >> 5, c4 = (i & 31) << 2;
        int gr = bm + row; if (gr >= N) gr = N - 1;
        float4 v = *(const float4*)&x[(size_t)gr * 128 + c4];
        __half2 h0 = __floats2half2_rn(v.x, v.y);
        __half2 h1 = __floats2half2_rn(v.z, v.w);
        uint2 o; o.x = *(unsigned*)&h0; o.y = *(unsigned*)&h1;
        *(uint2*)&Ah[row * APROW + c4] = o;
    }

    // B staging mapping
    const int srow = tid >> 1;
    const int shalf = (tid & 1) * 16;
    const unsigned dB = (unsigned)__cvta_generic_to_shared(&Bsb[srow * RPADH + shalf]);
    const unsigned Bbase = (unsigned)__cvta_generic_to_shared(Bsb);
    const unsigned Ahb = (unsigned)__cvta_generic_to_shared(Ah);

    // ldmatrix offsets
    const int arow = ((lane >> 3) & 1) * 8 + (lane & 7);
    const int akof = (lane >> 4) * 8;
    unsigned aoff[4];
#pragma unroll
    for (int mt = 0; mt < 4; mt++)
        aoff[mt] = (unsigned)(((wm * 64 + mt * 16 + arow) * APROW + akof) * 2);
    const int brow = (lane & 7) + ((lane >> 4) & 1) * 8;
    const int bkof = ((lane >> 3) & 1) * 8;
    unsigned boff[2];
#pragma unroll
    for (int p = 0; p < 2; p++)
        boff[p] = (unsigned)(((wn * 32 + p * 16 + brow) * RPADH + bkof) * 2);

    __syncthreads();   // A visible to all (also covers first B-ring use below)

    for (int slab = 0; slab < 3; slab++) {
        const __half* sB = g_wh + slab * 16384 + (size_t)srow * 128 + shalf;
        const int NK2 = 4;
#pragma unroll
        for (int p = 0; p < 2; p++) {
            cpasync16(dB + p * STH * 2, sB + p * 32);
            cpasync16(dB + p * STH * 2 + 16, sB + p * 32 + 8);
            cp_commit();
        }

        float acc[4][4][4] = {};
        for (int i = 0; i < NK2; i++) {
            cp_wait1();
            __syncthreads();
            const int nc = i + 2;
            if (nc < NK2) {
                const int sl = nc - (nc / 3) * 3;
                cpasync16(dB + sl * STH * 2, sB + nc * 32);
                cpasync16(dB + sl * STH * 2 + 16, sB + nc * 32 + 8);
            }
            cp_commit();

            const int buf = i - (i / 3) * 3;
            const unsigned sb = Bbase + buf * STH * 2;
#pragma unroll
            for (int s = 0; s < 2; s++) {
                const int kb = i * 32 + s * 16;   // k base within full row for A
                unsigned afr[4][4], bfr[4][2];
#pragma unroll
                for (int mt = 0; mt < 4; mt++)
                    ldmx4(afr[mt][0], afr[mt][1], afr[mt][2], afr[mt][3],
                          Ahb + aoff[mt] + kb * 2);
#pragma unroll
                for (int p = 0; p < 2; p++)
                    ldmx4(bfr[2 * p][0], bfr[2 * p][1], bfr[2 * p + 1][0],
                          bfr[2 * p + 1][1], sb + boff[p] + s * 32);
#pragma unroll
                for (int mt = 0; mt < 4; mt++)
#pragma unroll
                    for (int nt = 0; nt < 4; nt++)
                        mma_f16(acc[mt][nt], afr[mt], bfr[nt]);
            }
        }
        __syncthreads();   // all reads of B ring done before next slab overwrites

        // epilogue for this slab
#pragma unroll
        for (int nt = 0; nt < 4; nt++) {
            const int c0 = slab * 128 + wn * 32 + nt * 8 + 2 * tr;
#pragma unroll
            for (int mt = 0; mt < 4; mt++) {
                const int r0 = bm + wm * 64 + mt * 16 + tq;
                if (r0 < N) {
                    __half2 h = __floats2half2_rn(acc[mt][nt][0], acc[mt][nt][1]);
                    *(__half2*)&g_mh[(size_t)r0 * 384 + c0] = h;
                }
                const int r1 = r0 + 8;
                if (r1 < N) {
                    __half2 h = __floats2half2_rn(acc[mt][nt][2], acc[mt][nt][3]);
                    *(__half2*)&g_mh[(size_t)r1 * 384 + c0] = h;
                }
            }
        }
    }
}

// ---------------- aggregation: warp-per-(node,channel) segment stats ----------------
__device__ __forceinline__ float4 h4tof4(uint2 u) {
    __half2 a = *(__half2*)&u.x;
    __half2 b = *(__half2*)&u.y;
    float2 fa = __half22float2(a), fb = __half22float2(b);
    return make_float4(fa.x, fa.y, fb.x, fb.y);
}

__device__ __forceinline__ void agg_upd(float4 v, float s, float4& su, float4& sq,
                                        float4& mx, float4& mn) {
    float gx = v.x * s, gy = v.y * s, gz = v.z * s, gw = v.w * s;
    su.x += gx; su.y += gy; su.z += gz; su.w += gw;
    sq.x += gx * gx; sq.y += gy * gy; sq.z += gz * gz; sq.w += gw * gw;
    mx.x = fmaxf(mx.x, gx); mx.y = fmaxf(mx.y, gy); mx.z = fmaxf(mx.z, gz); mx.w = fmaxf(mx.w, gw);
    mn.x = fminf(mn.x, gx); mn.y = fminf(mn.y, gy); mn.z = fminf(mn.z, gz); mn.w = fminf(mn.w, gw);
}

__device__ __forceinline__ void sth4(__half* p, float4 v) {
    __half2 h0 = __floats2half2_rn(v.x, v.y);
    __half2 h1 = __floats2half2_rn(v.z, v.w);
    uint2 o; o.x = *(unsigned*)&h0; o.y = *(unsigned*)&h1;
    *(uint2*)p = o;
}

__global__ __launch_bounds__(256) void k_agg(const int* __restrict__ cols,
                                             const float* __restrict__ vA,
                                             const float* __restrict__ vC, int N) {
    int gw = (blockIdx.x * blockDim.x + threadIdx.x) >> 5;  // global warp
    int lane = threadIdx.x & 31;
    if (gw >= 3 * N) return;
    const int node = gw / 3;
    const int ch = gw - 3 * node;         // 0: vA, 1: vC, 2: vA*vC
    const int r0 = g_rowptr[node], r1 = g_rowptr[node + 1];

    const float NEG = -CUDART_INF_F, POS = CUDART_INF_F;
    float4 su = {0, 0, 0, 0}, sq = {0, 0, 0, 0};
    float4 mx = {NEG, NEG, NEG, NEG}, mn = {POS, POS, POS, POS};

    const __half* mbase = g_mh + (size_t)ch * 128 + lane * 4;

    int e = r0;
    for (; e + 4 <= r1; e += 4) {  // 4-edge unroll for load MLP
        int c0 = __ldg(cols + e),     c1 = __ldg(cols + e + 1);
        int c2 = __ldg(cols + e + 2), c3 = __ldg(cols + e + 3);
        float a0 = __ldg(vA + e),     a1 = __ldg(vA + e + 1);
        float a2 = __ldg(vA + e + 2), a3 = __ldg(vA + e + 3);
        float b0 = __ldg(vC + e),     b1 = __ldg(vC + e + 1);
        float b2 = __ldg(vC + e + 2), b3 = __ldg(vC + e + 3);
        float s0 = (ch == 0) ? a0 : (ch == 1) ? b0 : a0 * b0;
        float s1 = (ch == 0) ? a1 : (ch == 1) ? b1 : a1 * b1;
        float s2 = (ch == 0) ? a2 : (ch == 1) ? b2 : a2 * b2;
        float s3 = (ch == 0) ? a3 : (ch == 1) ? b3 : a3 * b3;
        uint2 u0 = __ldg((const uint2*)(mbase + (size_t)c0 * 384));
        uint2 u1 = __ldg((const uint2*)(mbase + (size_t)c1 * 384));
        uint2 u2 = __ldg((const uint2*)(mbase + (size_t)c2 * 384));
        uint2 u3 = __ldg((const uint2*)(mbase + (size_t)c3 * 384));
        agg_upd(h4tof4(u0), s0, su, sq, mx, mn);
        agg_upd(h4tof4(u1), s1, su, sq, mx, mn);
        agg_upd(h4tof4(u2), s2, su, sq, mx, mn);
        agg_upd(h4tof4(u3), s3, su, sq, mx, mn);
    }
    for (; e < r1; e++) {
        int c = __ldg(cols + e);
        float a = __ldg(vA + e);
        float b = __ldg(vC + e);
        float s = (ch == 0) ? a : (ch == 1) ? b : a * b;
        uint2 u = __ldg((const uint2*)(mbase + (size_t)c * 384));
        agg_upd(h4tof4(u), s, su, sq, mx, mn);
    }

    const int deg = r1 - r0;
    const float inv = 1.f / fmaxf((float)deg, 1.f);
    float4 mean, var, sd;
    mean.x = su.x * inv; mean.y = su.y * inv; mean.z = su.z * inv; mean.w = su.w * inv;
    var.x = fmaxf(sq.x * inv - mean.x * mean.x, 0.f);
    var.y = fmaxf(sq.y * inv - mean.y * mean.y, 0.f);
    var.z = fmaxf(sq.z * inv - mean.z * mean.z, 0.f);
    var.w = fmaxf(sq.w * inv - mean.w * mean.w, 0.f);
    sd.x = sqrtf(var.x + 1e-5f); sd.y = sqrtf(var.y + 1e-5f);
    sd.z = sqrtf(var.z + 1e-5f); sd.w = sqrtf(var.w + 1e-5f);
    if (deg == 0) {
        mx = make_float4(0.f, 0.f, 0.f, 0.f);
        mn = make_float4(0.f, 0.f, 0.f, 0.f);
    }
    __half* fb = g_fh + (size_t)node * 1536 + ch * 512 + lane * 4;
    sth4(fb,       mean);
    sth4(fb + 128, mx);
    sth4(fb + 256, mn);
    sth4(fb + 384, sd);
}

// ---------------- output GEMM (fp16 MMA): out = feats @ pw + sum(pna_b) ----------------
__global__ __launch_bounds__(256, 2) void k_out(const float* __restrict__ pb,
                                                float* __restrict__ out, int N) {
    extern __shared__ __align__(16) __half smh[];
    const int bm = blockIdx.x * 128;
    float acc[4][4][4] = {};
    gemm_fp16_core<48, 1536, 1536>(g_fh, g_pwh, acc, bm, N, smh);

    const int lane = threadIdx.x & 31;
    const int wid = threadIdx.x >> 5;
    const int wm = wid >> 2, wn = wid & 3;
    const int tq = lane >> 2, tr = lane & 3;
#pragma unroll
    for (int nt = 0; nt < 4; nt++) {
        const int c0 = wn * 32 + nt * 8 + 2 * tr;
        const float b0 = __ldg(pb + c0) + __ldg(pb + 128 + c0) + __ldg(pb + 256 + c0);
        const float b1 = __ldg(pb + c0 + 1) + __ldg(pb + 128 + c0 + 1) + __ldg(pb + 256 + c0 + 1);
#pragma unroll
        for (int mt = 0; mt < 4; mt++) {
            const int r0 = bm + wm * 64 + mt * 16 + tq;
            if (r0 < N) {
                float2 v = make_float2(acc[mt][nt][0] + b0, acc[mt][nt][1] + b1);
                *(float2*)&out[(size_t)r0 * 128 + c0] = v;
            }
            const int r1 = r0 + 8;
            if (r1 < N) {
                float2 v = make_float2(acc[mt][nt][2] + b0, acc[mt][nt][3] + b1);
                *(float2*)&out[(size_t)r1 * 128 + c0] = v;
            }
        }
    }
}

// ---------------- launch ----------------
extern "C" void kernel_launch(void* const* d_in, const int* in_sizes, int n_in,
                              void* d_out, int out_size) {
    const float* x    = (const float*)d_in[0];
    const int*   rows = (const int*)d_in[1];
    const int*   cols = (const int*)d_in[2];
    const float* vA   = (const float*)d_in[3];
    const float* vC   = (const float*)d_in[4];
    const float* W    = (const float*)d_in[5];
    const float* W2   = (const float*)d_in[6];
    const float* W3   = (const float*)d_in[7];
    const float* pw   = (const float*)d_in[8];  // [3,512,128] == flat [1536,128]
    const float* pb   = (const float*)d_in[9];  // [3,128]
    float* out = (float*)d_out;

    const int N = in_sizes[0] / 128;
    const int E = in_sizes[1];

    // idempotent, not stream-ordered; safe under graph capture
    cudaFuncSetAttribute(k_proj, cudaFuncAttributeMaxDynamicSharedMemorySize, PROJ_SMEM);
    cudaFuncSetAttribute(k_out,  cudaFuncAttributeMaxDynamicSharedMemorySize, GEMM_SMEM);

    __half *wh, *pwh;
    cudaGetSymbolAddress((void**)&wh,  g_wh);
    cudaGetSymbolAddress((void**)&pwh, g_pwh);

    k_rowptr<<<(N + 1 + 255) / 256, 256>>>(rows, E, N);

    dim3 gw3((16384 + 255) / 256, 3);
    k_cvt_w3<<<gw3, 256>>>(W, W2, W3, wh);
    k_cvt_t<<<(196608 + 255) / 256, 256>>>(pw, pwh, 1536, 128);

    k_proj<<<(N + 127) / 128, 256, PROJ_SMEM>>>(x, N);
    const int aggwarps = 3 * N;
    k_agg<<<(aggwarps + 7) / 8, 256>>>(cols, vA, vC, N);
    k_out<<<(N + 127) / 128, 256, GEMM_SMEM>>>(pb, out, N);
}